// round 5
// baseline (speedup 1.0000x reference)
#include <cuda_runtime.h>
#include <cuda_bf16.h>
#include <cstdint>

// Problem constants (fixed by the dataset)
#define BB   1024
#define TT   256
#define INDIM 128
#define HH   128
#define GG   384      // 3*H
#define HOR  24

// ---------------- scratch (device globals; no allocations allowed) ----------
__device__ float g_gx[(size_t)TT * BB * GG];        // 384 MB: x@w_i + b, [t][b][g]
__device__ float g_ys[(size_t)BB * TT * HH];        // 128 MB: hidden states, [b][t][j]
__device__ float g_W2[(size_t)TT * HH * HOR];       // 3 MB: folded mlp_w@fc_w_t@out_w, [t][j][p]
__device__ float g_bias_part[TT * HOR];
__device__ float g_final_bias[HOR];

// ---------------- packed f32x2 helpers (bit-exact vs 2x scalar) -------------
typedef unsigned long long u64;

__device__ __forceinline__ u64 pack2(float lo, float hi) {
    u64 r; asm("mov.b64 %0, {%1, %2};" : "=l"(r) : "f"(lo), "f"(hi)); return r;
}
__device__ __forceinline__ u64 dup2(float v) {
    u64 r; asm("mov.b64 %0, {%1, %1};" : "=l"(r) : "f"(v)); return r;
}
__device__ __forceinline__ void unpack2(u64 v, float& lo, float& hi) {
    asm("mov.b64 {%0, %1}, %2;" : "=f"(lo), "=f"(hi) : "l"(v));
}
__device__ __forceinline__ void ffma2(u64& d, u64 a, u64 b) {
    asm("fma.rn.f32x2 %0, %1, %2, %0;" : "+l"(d) : "l"(a), "l"(b));
}
__device__ __forceinline__ void fadd2(u64& d, u64 a) {
    asm("add.rn.f32x2 %0, %0, %1;" : "+l"(d) : "l"(a));
}

// ---------------- activation helpers ----------------------------------------
__device__ __forceinline__ float sigmoid_f(float x) {
    return 1.0f / (1.0f + __expf(-x));
}
__device__ __forceinline__ float tanh_f(float x) {
    float ax = fabsf(x);
    float e  = __expf(2.0f * ax);
    float r  = 1.0f - 2.0f / (e + 1.0f);
    return copysignf(r, x);
}

// ============================================================================
// Kernel 1: fold  W2_t = mlp_w @ (fc_w_t @ out_w)  and bias partial per t.
// ============================================================================
__global__ void __launch_bounds__(256) w2_kernel(
    const float* __restrict__ mlp_w,   // [128,512]
    const float* __restrict__ mlp_b,   // [512]
    const float* __restrict__ fc_w,    // [131072,128]
    const float* __restrict__ out_w)   // [128,24]
{
    extern __shared__ float sm[];
    float* ows    = sm;                 // 3072
    float* P      = sm + 3072;          // 12288
    float* rowbuf = sm + 3072 + 12288;  // 1024
    const int tid  = threadIdx.x;
    const int t    = blockIdx.x;
    const int warp = tid >> 5;
    const int lane = tid & 31;

    for (int i = tid; i < HH * HOR; i += 256) ows[i] = out_w[i];
    __syncthreads();

    const float* fcb = fc_w + (size_t)t * 512 * HH;
    for (int j = warp; j < 512; j += 8) {
        float4 v = ((const float4*)(fcb + (size_t)j * HH))[lane];
        ((float4*)(rowbuf + warp * 128))[lane] = v;
        __syncwarp();
        if (lane < HOR) {
            const float* rb = rowbuf + warp * 128;
            float acc = 0.0f;
            #pragma unroll 4
            for (int k = 0; k < 128; k++) acc = fmaf(rb[k], ows[k * HOR + lane], acc);
            P[j * HOR + lane] = acc;
        }
        __syncwarp();
    }
    __syncthreads();

    if (warp == 0 && lane < HOR) {
        float acc = 0.0f;
        for (int j = 0; j < 512; j++) acc = fmaf(mlp_b[j], P[j * HOR + lane], acc);
        g_bias_part[t * HOR + lane] = acc;
    }

    const int i  = tid & 127;
    const int p0 = (tid >> 7) * 12;
    float acc[12];
    #pragma unroll
    for (int q = 0; q < 12; q++) acc[q] = 0.0f;
    const float* mw = mlp_w + (size_t)i * 512;
    for (int j = 0; j < 512; j++) {
        float m = mw[j];
        const float* pr = P + j * HOR + p0;
        #pragma unroll
        for (int q = 0; q < 12; q++) acc[q] = fmaf(m, pr[q], acc[q]);
    }
    float* dst = g_W2 + ((size_t)t * HH + i) * HOR + p0;
    #pragma unroll
    for (int q = 0; q < 12; q++) dst[q] = acc[q];
}

// ============================================================================
// Kernel 2: final bias = sum_t bias_part + fc_b@out_w + out_b
// ============================================================================
__global__ void bias_final_kernel(const float* __restrict__ fc_b,
                                  const float* __restrict__ out_w,
                                  const float* __restrict__ out_b)
{
    int p = threadIdx.x;
    if (p >= HOR) return;
    float s = out_b[p];
    for (int t = 0; t < TT; t++) s += g_bias_part[t * HOR + p];
    for (int o = 0; o < HH; o++) s = fmaf(fc_b[o], out_w[o * HOR + p], s);
    g_final_bias[p] = s;
}

// ============================================================================
// Kernel 3: gx = x @ w_i + b  (FFMA2, unchanged from R4)
// ============================================================================
#define XT_LD 68
__global__ void __launch_bounds__(256, 1) gx_kernel(
    const float* __restrict__ x,     // [B][T][128]
    const float* __restrict__ w_i,   // [128][384]
    const float* __restrict__ bvec)  // [384]
{
    extern __shared__ float sm[];
    float* xT = sm;
    float* ws = sm + 128 * XT_LD;
    const int tid = threadIdx.x;
    const int m0  = blockIdx.x * 64;

    {
        int row = tid >> 2;
        int k0  = (tid & 3) * 32;
        const float* xrow = x + (size_t)(m0 + row) * INDIM + k0;
        #pragma unroll
        for (int u = 0; u < 8; u++) {
            float4 v = *(const float4*)(xrow + u * 4);
            int k = k0 + u * 4;
            xT[(k + 0) * XT_LD + row] = v.x;
            xT[(k + 1) * XT_LD + row] = v.y;
            xT[(k + 2) * XT_LD + row] = v.z;
            xT[(k + 3) * XT_LD + row] = v.w;
        }
    }
    {
        const float4* src = (const float4*)w_i;
        float4* dst = (float4*)ws;
        for (int idx = tid; idx < (128 * GG) / 4; idx += 256) dst[idx] = src[idx];
    }
    __syncthreads();

    const int g0  = (tid & 31) * 12;
    const int mr0 = (tid >> 5) * 8;
    u64 acc2[8][6];
    #pragma unroll
    for (int r = 0; r < 8; r++)
        #pragma unroll
        for (int q = 0; q < 6; q++) acc2[r][q] = 0ULL;

    #pragma unroll 2
    for (int k = 0; k < 128; k++) {
        float4 xa = *(const float4*)&xT[k * XT_LD + mr0];
        float4 xb = *(const float4*)&xT[k * XT_LD + mr0 + 4];
        const u64* wr = (const u64*)&ws[k * GG + g0];
        ulonglong2 wv0 = *(const ulonglong2*)(wr);
        ulonglong2 wv1 = *(const ulonglong2*)(wr + 2);
        ulonglong2 wv2 = *(const ulonglong2*)(wr + 4);
        u64 wq[6] = {wv0.x, wv0.y, wv1.x, wv1.y, wv2.x, wv2.y};
        u64 xd[8];
        xd[0] = dup2(xa.x); xd[1] = dup2(xa.y); xd[2] = dup2(xa.z); xd[3] = dup2(xa.w);
        xd[4] = dup2(xb.x); xd[5] = dup2(xb.y); xd[6] = dup2(xb.z); xd[7] = dup2(xb.w);
        #pragma unroll
        for (int r = 0; r < 8; r++)
            #pragma unroll
            for (int q = 0; q < 6; q++)
                ffma2(acc2[r][q], xd[r], wq[q]);
    }

    float bsr[12];
    #pragma unroll
    for (int q = 0; q < 12; q++) bsr[q] = __ldg(bvec + g0 + q);

    #pragma unroll
    for (int r = 0; r < 8; r++) {
        int m  = m0 + mr0 + r;
        int bb = m >> 8;
        int tt = m & 255;
        float* dst = g_gx + ((size_t)tt * BB + bb) * GG + g0;
        float av[12];
        #pragma unroll
        for (int q = 0; q < 6; q++) unpack2(acc2[r][q], av[2*q], av[2*q+1]);
        #pragma unroll
        for (int q = 0; q < 12; q += 4) {
            float4 o;
            o.x = av[q + 0] + bsr[q + 0];
            o.y = av[q + 1] + bsr[q + 1];
            o.z = av[q + 2] + bsr[q + 2];
            o.w = av[q + 3] + bsr[q + 3];
            *(float4*)(dst + q) = o;
        }
    }
}

// ============================================================================
// Kernel 4 (v4): recurrence with w_h ENTIRELY IN REGISTERS (96 regs/thread).
// 128 CTAs x 512 threads, 8 batch rows per CTA.
// Phase 1 (zr): thread = (col 0..255, khalf 0..1), 64 weight regs, k-split 2.
// Phase 2 (a):  thread = (c2 0..127, kq 0..3),     32 weight regs, k-split 4.
// Partial sums exchanged via smem in packed f32x2. h_t streamed to g_ys.
// Smem total: 24 KB (no weights!).
// ============================================================================
__global__ void __launch_bounds__(512, 1) rec_kernel(
    const float* __restrict__ w_h)   // [128][384]
{
    extern __shared__ float sm[];
    float* hT   = sm;                 // [k][r] 1024
    float* rhT  = sm + 1024;          // [k][r] 1024
    float* zs   = sm + 2048;          // [r][c] 1024
    u64*   xch  = (u64*)(sm + 3072);  // 1536 u64 (12 KB), shared by both phases

    const int tid = threadIdx.x;
    const int b0  = blockIdx.x * 8;

    // identities
    const int col = tid & 255;        // phase-1 gate column (z: 0..127, r: 128..255)
    const int kh  = tid >> 8;         // 0/1  k-half
    const int c2  = tid & 127;        // phase-2 a-gate column
    const int kq  = tid >> 7;         // 0..3 k-quarter

    // ---- load weight slices into registers (once) ----
    float wz[64];
    #pragma unroll
    for (int i = 0; i < 64; i++)
        wz[i] = __ldg(w_h + (size_t)(kh * 64 + i) * GG + col);
    float wa[32];
    #pragma unroll
    for (int i = 0; i < 32; i++)
        wa[i] = __ldg(w_h + (size_t)(kq * 32 + i) * GG + 256 + c2);

    for (int idx = tid; idx < 1024; idx += 512) hT[idx] = 0.0f;
    __syncthreads();

    for (int t = 0; t < TT; t++) {
        const float* gxt = g_gx + ((size_t)t * BB + b0) * GG;

        // gx prefetch: kh==1 threads (warps 8-15) carry gx1; kq==1 (warps 4-7) carry gx2
        float gxp[8];
        if (kh == 1) {
            #pragma unroll
            for (int r = 0; r < 8; r++) gxp[r] = __ldg(gxt + r * GG + col);
        } else if (kq == 1) {
            #pragma unroll
            for (int r = 0; r < 8; r++) gxp[r] = __ldg(gxt + r * GG + 256 + c2);
        }

        // ---- phase 1: zr partial dot over this thread's k-half ----
        u64 p1[4] = {0ULL, 0ULL, 0ULL, 0ULL};
        {
            const float* hp = hT + kh * 64 * 8;
            #pragma unroll
            for (int i = 0; i < 64; i++) {
                ulonglong2 h0 = *(const ulonglong2*)(hp + i * 8);
                ulonglong2 h1 = *(const ulonglong2*)(hp + i * 8 + 4);
                u64 wd = dup2(wz[i]);
                ffma2(p1[0], h0.x, wd);
                ffma2(p1[1], h0.y, wd);
                ffma2(p1[2], h1.x, wd);
                ffma2(p1[3], h1.y, wd);
            }
        }
        if (kh == 1) {   // fold gx into the k-high partial, then publish
            #pragma unroll
            for (int q = 0; q < 4; q++)
                fadd2(p1[q], pack2(gxp[2*q], gxp[2*q+1]));
            #pragma unroll
            for (int q = 0; q < 4; q++) xch[col * 4 + q] = p1[q];
        }
        __syncthreads();

        if (kh == 0) {   // combine + activate
            float a[8];
            #pragma unroll
            for (int q = 0; q < 4; q++) {
                fadd2(p1[q], xch[col * 4 + q]);
                unpack2(p1[q], a[2*q], a[2*q+1]);
            }
            if (col < 128) {                  // z gate
                #pragma unroll
                for (int r = 0; r < 8; r++)
                    zs[r * 128 + col] = sigmoid_f(a[r]);
            } else {                          // r gate -> rh = r .* h
                int j = col - 128;
                #pragma unroll
                for (int r = 0; r < 8; r++)
                    rhT[j * 8 + r] = sigmoid_f(a[r]) * hT[j * 8 + r];
            }
        }
        __syncthreads();

        // ---- phase 2: a-gate partial dot over this thread's k-quarter ----
        u64 p2[4] = {0ULL, 0ULL, 0ULL, 0ULL};
        {
            const float* rp = rhT + kq * 32 * 8;
            #pragma unroll
            for (int i = 0; i < 32; i++) {
                ulonglong2 r0 = *(const ulonglong2*)(rp + i * 8);
                ulonglong2 r1 = *(const ulonglong2*)(rp + i * 8 + 4);
                u64 wd = dup2(wa[i]);
                ffma2(p2[0], r0.x, wd);
                ffma2(p2[1], r0.y, wd);
                ffma2(p2[2], r1.x, wd);
                ffma2(p2[3], r1.y, wd);
            }
        }
        if (kq == 1) {   // fold gx_a into quarter-1 partial
            #pragma unroll
            for (int q = 0; q < 4; q++)
                fadd2(p2[q], pack2(gxp[2*q], gxp[2*q+1]));
        }
        if (kq > 0) {
            #pragma unroll
            for (int q = 0; q < 4; q++)
                xch[(c2 * 3 + (kq - 1)) * 4 + q] = p2[q];
        }
        __syncthreads();

        if (kq == 0) {   // combine + tanh + h update + stream h_t
            #pragma unroll
            for (int u = 0; u < 3; u++)
                #pragma unroll
                for (int q = 0; q < 4; q++)
                    fadd2(p2[q], xch[(c2 * 3 + u) * 4 + q]);
            float a[8];
            #pragma unroll
            for (int q = 0; q < 4; q++) unpack2(p2[q], a[2*q], a[2*q+1]);
            #pragma unroll
            for (int r = 0; r < 8; r++) {
                float av   = tanh_f(a[r]);
                float z    = zs[r * 128 + c2];
                float hold = hT[c2 * 8 + r];
                float hn   = fmaf(z, av - hold, hold);   // (1-z)h + z*a
                hT[c2 * 8 + r] = hn;
                g_ys[((size_t)(b0 + r) * TT + t) * HH + c2] = hn;
            }
        }
        __syncthreads();
    }
}

// ============================================================================
// Kernel 5: out[b,p] = sum_t sum_j ys[b,t,j] * W2[t,j,p] + final_bias[p]
// grid 128 CTAs (8 rows each) x 256 threads. W2_t staged in smem per t.
// thread = (r = tid>>5, jq = tid&31, j = jq*4). FFMA2 over p-pairs.
// ============================================================================
__global__ void __launch_bounds__(256, 1) fc_kernel(float* __restrict__ out)
{
    extern __shared__ float sm[];
    float* W2s  = sm;                 // 3072 floats (12 KB)
    float* part = sm;                 // reused at the end (6144 floats)

    const int tid = threadIdx.x;
    const int b0  = blockIdx.x * 8;
    const int r   = tid >> 5;
    const int jq  = tid & 31;
    const int j0  = jq * 4;

    u64 acc2[12];
    #pragma unroll
    for (int q = 0; q < 12; q++) acc2[q] = 0ULL;

    const float* ysrow = g_ys + (size_t)(b0 + r) * TT * HH;

    for (int t = 0; t < TT; t++) {
        // stage W2_t
        {
            const float4* src = (const float4*)(g_W2 + (size_t)t * HH * HOR);
            float4* dst = (float4*)W2s;
            for (int idx = tid; idx < (HH * HOR) / 4; idx += 256) dst[idx] = src[idx];
        }
        __syncthreads();

        float4 yv = *(const float4*)(ysrow + t * HH + j0);
        float yr[4] = {yv.x, yv.y, yv.z, yv.w};
        #pragma unroll
        for (int jj = 0; jj < 4; jj++) {
            u64 yd = dup2(yr[jj]);
            const u64* wp = (const u64*)(W2s + (j0 + jj) * HOR);
            ulonglong2 w0 = *(const ulonglong2*)(wp);
            ulonglong2 w1 = *(const ulonglong2*)(wp + 2);
            ulonglong2 w2 = *(const ulonglong2*)(wp + 4);
            ulonglong2 w3 = *(const ulonglong2*)(wp + 6);
            ulonglong2 w4 = *(const ulonglong2*)(wp + 8);
            ulonglong2 w5 = *(const ulonglong2*)(wp + 10);
            u64 wv[12] = {w0.x,w0.y,w1.x,w1.y,w2.x,w2.y,w3.x,w3.y,w4.x,w4.y,w5.x,w5.y};
            #pragma unroll
            for (int q = 0; q < 12; q++) ffma2(acc2[q], yd, wv[q]);
        }
        __syncthreads();
    }

    // deterministic reduction over jq (fixed order)
    #pragma unroll
    for (int q = 0; q < 12; q++) {
        float v0, v1;
        unpack2(acc2[q], v0, v1);
        part[(r * HOR + 2*q + 0) * 32 + jq] = v0;
        part[(r * HOR + 2*q + 1) * 32 + jq] = v1;
    }
    __syncthreads();

    if (tid < 8 * HOR) {
        int rr = tid / HOR;
        int p  = tid - rr * HOR;
        const float* pp = part + (rr * HOR + p) * 32;
        float s = 0.0f;
        #pragma unroll
        for (int c = 0; c < 32; c++) s += pp[c];
        out[(size_t)(b0 + rr) * HOR + p] = s + g_final_bias[p];
    }
}

// ============================================================================
// launch
// ============================================================================
extern "C" void kernel_launch(void* const* d_in, const int* in_sizes, int n_in,
                              void* d_out, int out_size)
{
    const float* x     = (const float*)d_in[0];
    const float* w_i   = (const float*)d_in[1];
    const float* w_h   = (const float*)d_in[2];
    const float* bvec  = (const float*)d_in[3];
    const float* mlp_w = (const float*)d_in[4];
    const float* mlp_b = (const float*)d_in[5];
    const float* fc_w  = (const float*)d_in[6];
    const float* fc_b  = (const float*)d_in[7];
    const float* out_w = (const float*)d_in[8];
    const float* out_b = (const float*)d_in[9];
    float* out = (float*)d_out;

    const int smem_w2  = (3072 + 12288 + 1024) * 4;   // 65536
    const int smem_gx  = (128 * XT_LD + 128 * GG) * 4;// 231424
    const int smem_rec = 6144 * 4;                    // 24576
    const int smem_fc  = 6144 * 4;                    // 24576

    cudaFuncSetAttribute(w2_kernel,  cudaFuncAttributeMaxDynamicSharedMemorySize, smem_w2);
    cudaFuncSetAttribute(gx_kernel,  cudaFuncAttributeMaxDynamicSharedMemorySize, smem_gx);
    cudaFuncSetAttribute(rec_kernel, cudaFuncAttributeMaxDynamicSharedMemorySize, smem_rec);
    cudaFuncSetAttribute(fc_kernel,  cudaFuncAttributeMaxDynamicSharedMemorySize, smem_fc);

    w2_kernel<<<TT, 256, smem_w2>>>(mlp_w, mlp_b, fc_w, out_w);
    bias_final_kernel<<<1, 32>>>(fc_b, out_w, out_b);
    gx_kernel<<<(BB * TT) / 64, 256, smem_gx>>>(x, w_i, bvec);
    rec_kernel<<<BB / 8, 512, smem_rec>>>(w_h);
    fc_kernel<<<BB / 8, 256, smem_fc>>>(out);
}

// round 6
// speedup vs baseline: 1.4708x; 1.4708x over previous
#include <cuda_runtime.h>
#include <cuda_bf16.h>
#include <cstdint>

// Problem constants (fixed by the dataset)
#define BB   1024
#define TT   256
#define INDIM 128
#define HH   128
#define GG   384      // 3*H
#define HOR  24

// ---------------- scratch (device globals; no allocations allowed) ----------
__device__ float g_gx[(size_t)TT * BB * GG];        // 384 MB: x@w_i + b, [t][b][g]
__device__ float g_ys[(size_t)TT * BB * HH];        // 128 MB: hidden states, [t][b][j]
__device__ float g_W2[(size_t)TT * HH * HOR];       // 3 MB: folded weights, [t][j][p]
__device__ float g_bias_part[TT * HOR];
__device__ float g_final_bias[HOR];

// ---------------- packed f32x2 helpers (bit-exact vs 2x scalar) -------------
typedef unsigned long long u64;

__device__ __forceinline__ u64 pack2(float lo, float hi) {
    u64 r; asm("mov.b64 %0, {%1, %2};" : "=l"(r) : "f"(lo), "f"(hi)); return r;
}
__device__ __forceinline__ u64 dup2(float v) {
    u64 r; asm("mov.b64 %0, {%1, %1};" : "=l"(r) : "f"(v)); return r;
}
__device__ __forceinline__ void unpack2(u64 v, float& lo, float& hi) {
    asm("mov.b64 {%0, %1}, %2;" : "=f"(lo), "=f"(hi) : "l"(v));
}
__device__ __forceinline__ void ffma2(u64& d, u64 a, u64 b) {
    asm("fma.rn.f32x2 %0, %1, %2, %0;" : "+l"(d) : "l"(a), "l"(b));
}
__device__ __forceinline__ void fadd2(u64& d, u64 a) {
    asm("add.rn.f32x2 %0, %0, %1;" : "+l"(d) : "l"(a));
}
__device__ __forceinline__ u64 shfl_xor_u64(u64 v, int m) {
    uint32_t lo = (uint32_t)v, hi = (uint32_t)(v >> 32);
    lo = __shfl_xor_sync(0xffffffffu, lo, m);
    hi = __shfl_xor_sync(0xffffffffu, hi, m);
    return ((u64)hi << 32) | (u64)lo;
}

// ---------------- activation helpers ----------------------------------------
__device__ __forceinline__ float sigmoid_f(float x) {
    return 1.0f / (1.0f + __expf(-x));
}
__device__ __forceinline__ float tanh_f(float x) {
    float ax = fabsf(x);
    float e  = __expf(2.0f * ax);
    float r  = 1.0f - 2.0f / (e + 1.0f);
    return copysignf(r, x);
}

// ============================================================================
// Kernel 1: fold  W2_t = mlp_w @ (fc_w_t @ out_w)  and bias partial per t.
// ============================================================================
__global__ void __launch_bounds__(256) w2_kernel(
    const float* __restrict__ mlp_w,   // [128,512]
    const float* __restrict__ mlp_b,   // [512]
    const float* __restrict__ fc_w,    // [131072,128]
    const float* __restrict__ out_w)   // [128,24]
{
    extern __shared__ float sm[];
    float* ows    = sm;                 // 3072
    float* P      = sm + 3072;          // 12288
    float* rowbuf = sm + 3072 + 12288;  // 1024
    const int tid  = threadIdx.x;
    const int t    = blockIdx.x;
    const int warp = tid >> 5;
    const int lane = tid & 31;

    for (int i = tid; i < HH * HOR; i += 256) ows[i] = out_w[i];
    __syncthreads();

    const float* fcb = fc_w + (size_t)t * 512 * HH;
    for (int j = warp; j < 512; j += 8) {
        float4 v = ((const float4*)(fcb + (size_t)j * HH))[lane];
        ((float4*)(rowbuf + warp * 128))[lane] = v;
        __syncwarp();
        if (lane < HOR) {
            const float* rb = rowbuf + warp * 128;
            float acc = 0.0f;
            #pragma unroll 4
            for (int k = 0; k < 128; k++) acc = fmaf(rb[k], ows[k * HOR + lane], acc);
            P[j * HOR + lane] = acc;
        }
        __syncwarp();
    }
    __syncthreads();

    if (warp == 0 && lane < HOR) {
        float acc = 0.0f;
        for (int j = 0; j < 512; j++) acc = fmaf(mlp_b[j], P[j * HOR + lane], acc);
        g_bias_part[t * HOR + lane] = acc;
    }

    const int i  = tid & 127;
    const int p0 = (tid >> 7) * 12;
    float acc[12];
    #pragma unroll
    for (int q = 0; q < 12; q++) acc[q] = 0.0f;
    const float* mw = mlp_w + (size_t)i * 512;
    for (int j = 0; j < 512; j++) {
        float m = mw[j];
        const float* pr = P + j * HOR + p0;
        #pragma unroll
        for (int q = 0; q < 12; q++) acc[q] = fmaf(m, pr[q], acc[q]);
    }
    float* dst = g_W2 + ((size_t)t * HH + i) * HOR + p0;
    #pragma unroll
    for (int q = 0; q < 12; q++) dst[q] = acc[q];
}

// ============================================================================
// Kernel 2: final bias = sum_t bias_part + fc_b@out_w + out_b
// ============================================================================
__global__ void bias_final_kernel(const float* __restrict__ fc_b,
                                  const float* __restrict__ out_w,
                                  const float* __restrict__ out_b)
{
    int p = threadIdx.x;
    if (p >= HOR) return;
    float s = out_b[p];
    for (int t = 0; t < TT; t++) s += g_bias_part[t * HOR + p];
    for (int o = 0; o < HH; o++) s = fmaf(fc_b[o], out_w[o * HOR + p], s);
    g_final_bias[p] = s;
}

// ============================================================================
// Kernel 3: gx = x @ w_i + b  (FFMA2, unchanged)
// ============================================================================
#define XT_LD 68
__global__ void __launch_bounds__(256, 1) gx_kernel(
    const float* __restrict__ x,     // [B][T][128]
    const float* __restrict__ w_i,   // [128][384]
    const float* __restrict__ bvec)  // [384]
{
    extern __shared__ float sm[];
    float* xT = sm;
    float* ws = sm + 128 * XT_LD;
    const int tid = threadIdx.x;
    const int m0  = blockIdx.x * 64;

    {
        int row = tid >> 2;
        int k0  = (tid & 3) * 32;
        const float* xrow = x + (size_t)(m0 + row) * INDIM + k0;
        #pragma unroll
        for (int u = 0; u < 8; u++) {
            float4 v = *(const float4*)(xrow + u * 4);
            int k = k0 + u * 4;
            xT[(k + 0) * XT_LD + row] = v.x;
            xT[(k + 1) * XT_LD + row] = v.y;
            xT[(k + 2) * XT_LD + row] = v.z;
            xT[(k + 3) * XT_LD + row] = v.w;
        }
    }
    {
        const float4* src = (const float4*)w_i;
        float4* dst = (float4*)ws;
        for (int idx = tid; idx < (128 * GG) / 4; idx += 256) dst[idx] = src[idx];
    }
    __syncthreads();

    const int g0  = (tid & 31) * 12;
    const int mr0 = (tid >> 5) * 8;
    u64 acc2[8][6];
    #pragma unroll
    for (int r = 0; r < 8; r++)
        #pragma unroll
        for (int q = 0; q < 6; q++) acc2[r][q] = 0ULL;

    #pragma unroll 2
    for (int k = 0; k < 128; k++) {
        float4 xa = *(const float4*)&xT[k * XT_LD + mr0];
        float4 xb = *(const float4*)&xT[k * XT_LD + mr0 + 4];
        const u64* wr = (const u64*)&ws[k * GG + g0];
        ulonglong2 wv0 = *(const ulonglong2*)(wr);
        ulonglong2 wv1 = *(const ulonglong2*)(wr + 2);
        ulonglong2 wv2 = *(const ulonglong2*)(wr + 4);
        u64 wq[6] = {wv0.x, wv0.y, wv1.x, wv1.y, wv2.x, wv2.y};
        u64 xd[8];
        xd[0] = dup2(xa.x); xd[1] = dup2(xa.y); xd[2] = dup2(xa.z); xd[3] = dup2(xa.w);
        xd[4] = dup2(xb.x); xd[5] = dup2(xb.y); xd[6] = dup2(xb.z); xd[7] = dup2(xb.w);
        #pragma unroll
        for (int r = 0; r < 8; r++)
            #pragma unroll
            for (int q = 0; q < 6; q++)
                ffma2(acc2[r][q], xd[r], wq[q]);
    }

    float bsr[12];
    #pragma unroll
    for (int q = 0; q < 12; q++) bsr[q] = __ldg(bvec + g0 + q);

    #pragma unroll
    for (int r = 0; r < 8; r++) {
        int m  = m0 + mr0 + r;
        int bb = m >> 8;
        int tt = m & 255;
        float* dst = g_gx + ((size_t)tt * BB + bb) * GG + g0;
        float av[12];
        #pragma unroll
        for (int q = 0; q < 6; q++) unpack2(acc2[r][q], av[2*q], av[2*q+1]);
        #pragma unroll
        for (int q = 0; q < 12; q += 4) {
            float4 o;
            o.x = av[q + 0] + bsr[q + 0];
            o.y = av[q + 1] + bsr[q + 1];
            o.z = av[q + 2] + bsr[q + 2];
            o.w = av[q + 3] + bsr[q + 3];
            *(float4*)(dst + q) = o;
        }
    }
}

// ============================================================================
// Kernel 4 (v5): recurrence, w_h in registers, warp-shuffle k-split combine.
// 128 CTAs x 512 threads, 8 batch rows per CTA, 2 barriers per step.
// Phase 1 (zr): lane = (col%16, kh=lane>>4); k-split 2, combine shfl_xor(16).
//               lane kh handles rows 4kh..4kh+3.
// Phase 2 (a):  lane = (c2%8, kq=lane>>3);  k-split 4, combine shfl_xor(8,16).
//               lane kq handles rows 2kq..2kq+1.
// hT bank-interleaved by k-half:   idx_h(k) = ((k&63)<<1)|(k>>6)
// rhT bank-interleaved by k-quarter: idx_r(j) = ((j&31)<<2)|(j>>5)
// ============================================================================
__global__ void __launch_bounds__(512, 1) rec_kernel(
    const float* __restrict__ w_h)   // [128][384]
{
    __shared__ float hT[1024];
    __shared__ float rhT[1024];
    __shared__ float zs[1024];

    const int tid = threadIdx.x;
    const int w   = tid >> 5;
    const int l   = tid & 31;
    const int b0  = blockIdx.x * 8;

    // phase-1 identity
    const int col = w * 16 + (l & 15);     // 0..255 (z: 0..127, r: 128..255)
    const int kh  = l >> 4;                // 0/1
    const int rh0 = kh * 4;                // rows rh0..rh0+3
    // phase-2 identity
    const int c2  = w * 8 + (l & 7);       // 0..127
    const int kq  = l >> 3;                // 0..3
    const int r0v = 2 * kq;                // rows r0v, r0v+1

    // interleaved smem indices (precomputed)
    const int hidx = (((c2 & 63) << 1) | (c2 >> 6)) * 8;   // hT slot for c2
    const int jj   = col - 128;                            // r-gate j (warps 8-15)
    const int rjdx = (((jj & 31) << 2) | ((jj >> 5) & 3)) * 8;
    const int hjdx = (((jj & 63) << 1) | ((jj >> 6) & 1)) * 8;

    // ---- weights into registers (once) ----
    float wz[64];
    #pragma unroll
    for (int i = 0; i < 64; i++)
        wz[i] = __ldg(w_h + (size_t)(kh * 64 + i) * GG + col);
    float wa[32];
    #pragma unroll
    for (int i = 0; i < 32; i++)
        wa[i] = __ldg(w_h + (size_t)(kq * 32 + i) * GG + 256 + c2);

    for (int i = tid; i < 1024; i += 512) hT[i] = 0.0f;
    __syncthreads();

    for (int t = 0; t < TT; t++) {
        const float* gxt = g_gx + ((size_t)t * BB + b0) * GG;

        // prefetch gx for both phases (hidden under phase-1 k-loop)
        float gx1[4];
        #pragma unroll
        for (int u = 0; u < 4; u++) gx1[u] = __ldg(gxt + (rh0 + u) * GG + col);
        float gx2a = __ldg(gxt + (r0v + 0) * GG + 256 + c2);
        float gx2b = __ldg(gxt + (r0v + 1) * GG + 256 + c2);

        // ---- phase 1: zr partial dots over this lane's k-half ----
        u64 p1[4] = {0ULL, 0ULL, 0ULL, 0ULL};
        {
            const float* hp = hT + kh * 8;    // element (2i+kh)*8 = i*16 + kh*8
            #pragma unroll
            for (int i = 0; i < 64; i++) {
                ulonglong2 h0 = *(const ulonglong2*)(hp + i * 16);
                ulonglong2 h1 = *(const ulonglong2*)(hp + i * 16 + 4);
                u64 wd = dup2(wz[i]);
                ffma2(p1[0], h0.x, wd);
                ffma2(p1[1], h0.y, wd);
                ffma2(p1[2], h1.x, wd);
                ffma2(p1[3], h1.y, wd);
            }
        }
        // combine across k-halves (partner lane = l ^ 16)
        #pragma unroll
        for (int q = 0; q < 4; q++) fadd2(p1[q], shfl_xor_u64(p1[q], 16));

        {
            u64 pa = (kh == 0) ? p1[0] : p1[2];
            u64 pb = (kh == 0) ? p1[1] : p1[3];
            float a[4];
            unpack2(pa, a[0], a[1]);
            unpack2(pb, a[2], a[3]);
            if (col < 128) {                  // z gate (warps 0-7)
                #pragma unroll
                for (int u = 0; u < 4; u++)
                    zs[(rh0 + u) * 128 + col] = sigmoid_f(a[u] + gx1[u]);
            } else {                          // r gate -> rh = r .* h (warps 8-15)
                float4 hv = *(const float4*)&hT[hjdx + rh0];
                float4 o;
                o.x = sigmoid_f(a[0] + gx1[0]) * hv.x;
                o.y = sigmoid_f(a[1] + gx1[1]) * hv.y;
                o.z = sigmoid_f(a[2] + gx1[2]) * hv.z;
                o.w = sigmoid_f(a[3] + gx1[3]) * hv.w;
                *(float4*)&rhT[rjdx + rh0] = o;
            }
        }
        __syncthreads();

        // ---- phase 2: a-gate partial dots over this lane's k-quarter ----
        u64 p2[4] = {0ULL, 0ULL, 0ULL, 0ULL};
        {
            const float* rp = rhT + kq * 8;   // element (4i+kq)*8 = i*32 + kq*8
            #pragma unroll
            for (int i = 0; i < 32; i++) {
                ulonglong2 r0 = *(const ulonglong2*)(rp + i * 32);
                ulonglong2 r1 = *(const ulonglong2*)(rp + i * 32 + 4);
                u64 wd = dup2(wa[i]);
                ffma2(p2[0], r0.x, wd);
                ffma2(p2[1], r0.y, wd);
                ffma2(p2[2], r1.x, wd);
                ffma2(p2[3], r1.y, wd);
            }
        }
        // combine across 4 k-quarters (lane bits 3,4)
        #pragma unroll
        for (int q = 0; q < 4; q++) {
            fadd2(p2[q], shfl_xor_u64(p2[q], 8));
            fadd2(p2[q], shfl_xor_u64(p2[q], 16));
        }

        {
            u64 pc = (kq & 2) ? ((kq & 1) ? p2[3] : p2[2])
                              : ((kq & 1) ? p2[1] : p2[0]);
            float aa0, aa1;
            unpack2(pc, aa0, aa1);
            float z0 = zs[(r0v + 0) * 128 + c2];
            float z1 = zs[(r0v + 1) * 128 + c2];
            float h0 = hT[hidx + r0v + 0];
            float h1 = hT[hidx + r0v + 1];
            float hn0 = fmaf(z0, tanh_f(aa0 + gx2a) - h0, h0);
            float hn1 = fmaf(z1, tanh_f(aa1 + gx2b) - h1, h1);
            hT[hidx + r0v + 0] = hn0;
            hT[hidx + r0v + 1] = hn1;
            size_t yb = ((size_t)t * BB + b0 + r0v) * HH + c2;
            g_ys[yb]      = hn0;
            g_ys[yb + HH] = hn1;
        }
        __syncthreads();
    }
}

// ============================================================================
// Kernel 5 (v2): out[b,p] = sum_t sum_j ys[t,b,j]*W2[t,j,p] + bias.
// 128 CTAs x 512 threads. Thread = (j = tid&127, g = tid>>7 -> rows 2g,2g+1).
// No smem in the hot loop; W2 rows straight from L2, ys from DRAM.
// Deterministic warp-butterfly + tiny smem reduce at the end.
// ============================================================================
__global__ void __launch_bounds__(512, 1) fc_kernel(float* __restrict__ out)
{
    __shared__ float red[8 * HOR * 4];    // [row][p][jblk] = 768 floats

    const int tid = threadIdx.x;
    const int j   = tid & 127;
    const int g   = tid >> 7;             // 0..3 -> rows 2g, 2g+1
    const int b0  = blockIdx.x * 8;
    const int lane = tid & 31;
    const int jblk = (j >> 5);             // 0..3

    u64 acc[2][12];
    #pragma unroll
    for (int u = 0; u < 2; u++)
        #pragma unroll
        for (int q = 0; q < 12; q++) acc[u][q] = 0ULL;

    #pragma unroll 2
    for (int t = 0; t < TT; t++) {
        const float* ysp = g_ys + ((size_t)t * BB + b0 + 2 * g) * HH + j;
        float y0 = __ldg(ysp);
        float y1 = __ldg(ysp + HH);
        const ulonglong2* wp = (const ulonglong2*)(g_W2 + ((size_t)t * HH + j) * HOR);
        ulonglong2 w0 = wp[0], w1 = wp[1], w2 = wp[2],
                   w3 = wp[3], w4 = wp[4], w5 = wp[5];
        u64 wq[12] = {w0.x, w0.y, w1.x, w1.y, w2.x, w2.y,
                      w3.x, w3.y, w4.x, w4.y, w5.x, w5.y};
        u64 y0d = dup2(y0), y1d = dup2(y1);
        #pragma unroll
        for (int q = 0; q < 12; q++) {
            ffma2(acc[0][q], y0d, wq[q]);
            ffma2(acc[1][q], y1d, wq[q]);
        }
    }

    // warp butterfly over 32 consecutive j's (deterministic fixed order)
    #pragma unroll
    for (int u = 0; u < 2; u++)
        #pragma unroll
        for (int q = 0; q < 12; q++) {
            fadd2(acc[u][q], shfl_xor_u64(acc[u][q], 1));
            fadd2(acc[u][q], shfl_xor_u64(acc[u][q], 2));
            fadd2(acc[u][q], shfl_xor_u64(acc[u][q], 4));
            fadd2(acc[u][q], shfl_xor_u64(acc[u][q], 8));
            fadd2(acc[u][q], shfl_xor_u64(acc[u][q], 16));
        }

    if (lane == 0) {
        #pragma unroll
        for (int u = 0; u < 2; u++) {
            int row = 2 * g + u;
            #pragma unroll
            for (int q = 0; q < 12; q++) {
                float v0, v1;
                unpack2(acc[u][q], v0, v1);
                red[(row * HOR + 2 * q + 0) * 4 + jblk] = v0;
                red[(row * HOR + 2 * q + 1) * 4 + jblk] = v1;
            }
        }
    }
    __syncthreads();

    if (tid < 8 * HOR) {
        int row = tid / HOR;
        int p   = tid - row * HOR;
        const float* pp = red + (row * HOR + p) * 4;
        float s = ((pp[0] + pp[1]) + pp[2]) + pp[3];
        out[(size_t)(b0 + row) * HOR + p] = s + g_final_bias[p];
    }
}

// ============================================================================
// launch
// ============================================================================
extern "C" void kernel_launch(void* const* d_in, const int* in_sizes, int n_in,
                              void* d_out, int out_size)
{
    const float* x     = (const float*)d_in[0];
    const float* w_i   = (const float*)d_in[1];
    const float* w_h   = (const float*)d_in[2];
    const float* bvec  = (const float*)d_in[3];
    const float* mlp_w = (const float*)d_in[4];
    const float* mlp_b = (const float*)d_in[5];
    const float* fc_w  = (const float*)d_in[6];
    const float* fc_b  = (const float*)d_in[7];
    const float* out_w = (const float*)d_in[8];
    const float* out_b = (const float*)d_in[9];
    float* out = (float*)d_out;

    const int smem_w2  = (3072 + 12288 + 1024) * 4;   // 65536
    const int smem_gx  = (128 * XT_LD + 128 * GG) * 4;// 231424

    cudaFuncSetAttribute(w2_kernel,  cudaFuncAttributeMaxDynamicSharedMemorySize, smem_w2);
    cudaFuncSetAttribute(gx_kernel,  cudaFuncAttributeMaxDynamicSharedMemorySize, smem_gx);

    w2_kernel<<<TT, 256, smem_w2>>>(mlp_w, mlp_b, fc_w, out_w);
    bias_final_kernel<<<1, 32>>>(fc_b, out_w, out_b);
    gx_kernel<<<(BB * TT) / 64, 256, smem_gx>>>(x, w_i, bvec);
    rec_kernel<<<BB / 8, 512>>>(w_h);
    fc_kernel<<<BB / 8, 512>>>(out);
}

// round 7
// speedup vs baseline: 1.5419x; 1.0483x over previous
#include <cuda_runtime.h>
#include <cuda_bf16.h>
#include <cstdint>

// Problem constants (fixed by the dataset)
#define BB   1024
#define TT   256
#define INDIM 128
#define HH   128
#define GG   384      // 3*H
#define HOR  24

// ---------------- scratch (device globals; no allocations allowed) ----------
__device__ float g_gx[(size_t)TT * BB * GG];        // 384 MB: x@w_i + b, [t][b][g]
__device__ float g_ys[(size_t)TT * BB * HH];        // 128 MB: hidden states, [t][b][j]
__device__ float g_W2[(size_t)TT * HH * HOR];       // 3 MB: folded weights, [t][j][p]
__device__ float g_bias_part[TT * HOR];
__device__ float g_final_bias[HOR];

// ---------------- packed f32x2 helpers (bit-exact vs 2x scalar) -------------
typedef unsigned long long u64;

__device__ __forceinline__ u64 pack2(float lo, float hi) {
    u64 r; asm("mov.b64 %0, {%1, %2};" : "=l"(r) : "f"(lo), "f"(hi)); return r;
}
__device__ __forceinline__ u64 dup2(float v) {
    u64 r; asm("mov.b64 %0, {%1, %1};" : "=l"(r) : "f"(v)); return r;
}
__device__ __forceinline__ void unpack2(u64 v, float& lo, float& hi) {
    asm("mov.b64 {%0, %1}, %2;" : "=f"(lo), "=f"(hi) : "l"(v));
}
__device__ __forceinline__ void ffma2(u64& d, u64 a, u64 b) {
    asm("fma.rn.f32x2 %0, %1, %2, %0;" : "+l"(d) : "l"(a), "l"(b));
}
__device__ __forceinline__ void fadd2(u64& d, u64 a) {
    asm("add.rn.f32x2 %0, %0, %1;" : "+l"(d) : "l"(a));
}
__device__ __forceinline__ u64 shfl_xor_u64(u64 v, int m) {
    uint32_t lo = (uint32_t)v, hi = (uint32_t)(v >> 32);
    lo = __shfl_xor_sync(0xffffffffu, lo, m);
    hi = __shfl_xor_sync(0xffffffffu, hi, m);
    return ((u64)hi << 32) | (u64)lo;
}

// ---------------- activation helpers ----------------------------------------
__device__ __forceinline__ float sigmoid_f(float x) {
    return 1.0f / (1.0f + __expf(-x));
}
__device__ __forceinline__ float tanh_f(float x) {
    float ax = fabsf(x);
    float e  = __expf(2.0f * ax);
    float r  = 1.0f - 2.0f / (e + 1.0f);
    return copysignf(r, x);
}

// ============================================================================
// Kernel 1: fold  W2_t = mlp_w @ (fc_w_t @ out_w)  and bias partial per t.
// ============================================================================
__global__ void __launch_bounds__(256) w2_kernel(
    const float* __restrict__ mlp_w,   // [128,512]
    const float* __restrict__ mlp_b,   // [512]
    const float* __restrict__ fc_w,    // [131072,128]
    const float* __restrict__ out_w)   // [128,24]
{
    extern __shared__ float sm[];
    float* ows    = sm;                 // 3072
    float* P      = sm + 3072;          // 12288
    float* rowbuf = sm + 3072 + 12288;  // 1024
    const int tid  = threadIdx.x;
    const int t    = blockIdx.x;
    const int warp = tid >> 5;
    const int lane = tid & 31;

    for (int i = tid; i < HH * HOR; i += 256) ows[i] = out_w[i];
    __syncthreads();

    const float* fcb = fc_w + (size_t)t * 512 * HH;
    for (int j = warp; j < 512; j += 8) {
        float4 v = ((const float4*)(fcb + (size_t)j * HH))[lane];
        ((float4*)(rowbuf + warp * 128))[lane] = v;
        __syncwarp();
        if (lane < HOR) {
            const float* rb = rowbuf + warp * 128;
            float acc = 0.0f;
            #pragma unroll 4
            for (int k = 0; k < 128; k++) acc = fmaf(rb[k], ows[k * HOR + lane], acc);
            P[j * HOR + lane] = acc;
        }
        __syncwarp();
    }
    __syncthreads();

    if (warp == 0 && lane < HOR) {
        float acc = 0.0f;
        for (int j = 0; j < 512; j++) acc = fmaf(mlp_b[j], P[j * HOR + lane], acc);
        g_bias_part[t * HOR + lane] = acc;
    }

    const int i  = tid & 127;
    const int p0 = (tid >> 7) * 12;
    float acc[12];
    #pragma unroll
    for (int q = 0; q < 12; q++) acc[q] = 0.0f;
    const float* mw = mlp_w + (size_t)i * 512;
    for (int j = 0; j < 512; j++) {
        float m = mw[j];
        const float* pr = P + j * HOR + p0;
        #pragma unroll
        for (int q = 0; q < 12; q++) acc[q] = fmaf(m, pr[q], acc[q]);
    }
    float* dst = g_W2 + ((size_t)t * HH + i) * HOR + p0;
    #pragma unroll
    for (int q = 0; q < 12; q++) dst[q] = acc[q];
}

// ============================================================================
// Kernel 2: final bias = sum_t bias_part + fc_b@out_w + out_b
// ============================================================================
__global__ void bias_final_kernel(const float* __restrict__ fc_b,
                                  const float* __restrict__ out_w,
                                  const float* __restrict__ out_b)
{
    int p = threadIdx.x;
    if (p >= HOR) return;
    float s = out_b[p];
    for (int t = 0; t < TT; t++) s += g_bias_part[t * HOR + p];
    for (int o = 0; o < HH; o++) s = fmaf(fc_b[o], out_w[o * HOR + p], s);
    g_final_bias[p] = s;
}

// ============================================================================
// Kernel 3 (v4): gx = x @ w_i + b.  CONFLICT-FREE column ownership:
// thread owns cols {gate*128 + 4c .. +3} for each of the 3 gates (c = lane).
// All w-loads are LDS.128 at 16B lane stride (minimum wavefronts, 0 conflict);
// stores are 512B-contiguous per (row, gate).
// ============================================================================
#define XT_LD 68
__global__ void __launch_bounds__(256, 1) gx_kernel(
    const float* __restrict__ x,     // [B][T][128]
    const float* __restrict__ w_i,   // [128][384]
    const float* __restrict__ bvec)  // [384]
{
    extern __shared__ float sm[];
    float* xT = sm;                        // 128*68 floats
    float* ws = sm + 128 * XT_LD;          // 49152 floats
    const int tid = threadIdx.x;
    const int m0  = blockIdx.x * 64;

    // stage x tile transposed: xT[k][m]
    {
        int row = tid >> 2;
        int k0  = (tid & 3) * 32;
        const float* xrow = x + (size_t)(m0 + row) * INDIM + k0;
        #pragma unroll
        for (int u = 0; u < 8; u++) {
            float4 v = *(const float4*)(xrow + u * 4);
            int k = k0 + u * 4;
            xT[(k + 0) * XT_LD + row] = v.x;
            xT[(k + 1) * XT_LD + row] = v.y;
            xT[(k + 2) * XT_LD + row] = v.z;
            xT[(k + 3) * XT_LD + row] = v.w;
        }
    }
    // stage w_i
    {
        const float4* src = (const float4*)w_i;
        float4* dst = (float4*)ws;
        for (int idx = tid; idx < (128 * GG) / 4; idx += 256) dst[idx] = src[idx];
    }
    __syncthreads();

    const int c   = tid & 31;          // column quad within each gate
    const int mr0 = (tid >> 5) * 8;    // 8 rows per thread
    // accumulators: 8 rows x 3 gates x 2 packed-pairs (cols 4c..4c+3)
    u64 acc2[8][6];
    #pragma unroll
    for (int r = 0; r < 8; r++)
        #pragma unroll
        for (int q = 0; q < 6; q++) acc2[r][q] = 0ULL;

    #pragma unroll 2
    for (int k = 0; k < 128; k++) {
        float4 xa = *(const float4*)&xT[k * XT_LD + mr0];
        float4 xb = *(const float4*)&xT[k * XT_LD + mr0 + 4];
        const u64* wk = (const u64*)&ws[k * GG];       // k*192 u64
        ulonglong2 wg0 = *(const ulonglong2*)(wk +       2 * c);   // gate 0
        ulonglong2 wg1 = *(const ulonglong2*)(wk +  64 + 2 * c);   // gate 1
        ulonglong2 wg2 = *(const ulonglong2*)(wk + 128 + 2 * c);   // gate 2
        u64 wq[6] = {wg0.x, wg0.y, wg1.x, wg1.y, wg2.x, wg2.y};
        u64 xd[8];
        xd[0] = dup2(xa.x); xd[1] = dup2(xa.y); xd[2] = dup2(xa.z); xd[3] = dup2(xa.w);
        xd[4] = dup2(xb.x); xd[5] = dup2(xb.y); xd[6] = dup2(xb.z); xd[7] = dup2(xb.w);
        #pragma unroll
        for (int r = 0; r < 8; r++)
            #pragma unroll
            for (int q = 0; q < 6; q++)
                ffma2(acc2[r][q], xd[r], wq[q]);
    }

    float bsr[12];
    #pragma unroll
    for (int g = 0; g < 3; g++)
        #pragma unroll
        for (int u = 0; u < 4; u++)
            bsr[g * 4 + u] = __ldg(bvec + g * 128 + 4 * c + u);

    #pragma unroll
    for (int r = 0; r < 8; r++) {
        int m  = m0 + mr0 + r;
        int bb = m >> 8;
        int tt = m & 255;
        float* dst = g_gx + ((size_t)tt * BB + bb) * GG;
        #pragma unroll
        for (int g = 0; g < 3; g++) {
            float v0, v1, v2, v3;
            unpack2(acc2[r][2 * g + 0], v0, v1);
            unpack2(acc2[r][2 * g + 1], v2, v3);
            float4 o;
            o.x = v0 + bsr[g * 4 + 0];
            o.y = v1 + bsr[g * 4 + 1];
            o.z = v2 + bsr[g * 4 + 2];
            o.w = v3 + bsr[g * 4 + 3];
            *(float4*)(dst + g * 128 + 4 * c) = o;
        }
    }
}

// ============================================================================
// Kernel 4 (v6): recurrence, w_h in registers, warp-shuffle k-split combine,
// gx1 software-pipelined one step ahead (issued after its last use, covered by
// barrier + phase-2 + next phase-1 k-loop).
// ============================================================================
__global__ void __launch_bounds__(512, 1) rec_kernel(
    const float* __restrict__ w_h)   // [128][384]
{
    __shared__ float hT[1024];
    __shared__ float rhT[1024];
    __shared__ float zs[1024];

    const int tid = threadIdx.x;
    const int w   = tid >> 5;
    const int l   = tid & 31;
    const int b0  = blockIdx.x * 8;

    // phase-1 identity
    const int col = w * 16 + (l & 15);     // 0..255 (z: 0..127, r: 128..255)
    const int kh  = l >> 4;                // 0/1
    const int rh0 = kh * 4;                // rows rh0..rh0+3
    // phase-2 identity
    const int c2  = w * 8 + (l & 7);       // 0..127
    const int kq  = l >> 3;                // 0..3
    const int r0v = 2 * kq;                // rows r0v, r0v+1

    // interleaved smem indices
    const int hidx = (((c2 & 63) << 1) | (c2 >> 6)) * 8;
    const int jj   = col - 128;
    const int rjdx = (((jj & 31) << 2) | ((jj >> 5) & 3)) * 8;
    const int hjdx = (((jj & 63) << 1) | ((jj >> 6) & 1)) * 8;

    // ---- weights into registers (once) ----
    float wz[64];
    #pragma unroll
    for (int i = 0; i < 64; i++)
        wz[i] = __ldg(w_h + (size_t)(kh * 64 + i) * GG + col);
    float wa[32];
    #pragma unroll
    for (int i = 0; i < 32; i++)
        wa[i] = __ldg(w_h + (size_t)(kq * 32 + i) * GG + 256 + c2);

    for (int i = tid; i < 1024; i += 512) hT[i] = 0.0f;
    __syncthreads();

    // prime gx1 for step 0
    float gx1[4];
    {
        const float* gx0 = g_gx + (size_t)b0 * GG;
        #pragma unroll
        for (int u = 0; u < 4; u++) gx1[u] = __ldg(gx0 + (rh0 + u) * GG + col);
    }

    for (int t = 0; t < TT; t++) {
        const float* gxt = g_gx + ((size_t)t * BB + b0) * GG;

        // gx2 issued here, consumed at end of phase-2 (~650 cyc cover)
        float gx2a = __ldg(gxt + (r0v + 0) * GG + 256 + c2);
        float gx2b = __ldg(gxt + (r0v + 1) * GG + 256 + c2);

        // ---- phase 1: zr partial dots over this lane's k-half ----
        u64 p1[4] = {0ULL, 0ULL, 0ULL, 0ULL};
        {
            const float* hp = hT + kh * 8;
            #pragma unroll
            for (int i = 0; i < 64; i++) {
                ulonglong2 h0 = *(const ulonglong2*)(hp + i * 16);
                ulonglong2 h1 = *(const ulonglong2*)(hp + i * 16 + 4);
                u64 wd = dup2(wz[i]);
                ffma2(p1[0], h0.x, wd);
                ffma2(p1[1], h0.y, wd);
                ffma2(p1[2], h1.x, wd);
                ffma2(p1[3], h1.y, wd);
            }
        }
        // combine across k-halves (partner lane = l ^ 16)
        #pragma unroll
        for (int q = 0; q < 4; q++) fadd2(p1[q], shfl_xor_u64(p1[q], 16));

        {
            u64 pa = (kh == 0) ? p1[0] : p1[2];
            u64 pb = (kh == 0) ? p1[1] : p1[3];
            float a[4];
            unpack2(pa, a[0], a[1]);
            unpack2(pb, a[2], a[3]);
            if (col < 128) {                  // z gate (warps 0-7)
                #pragma unroll
                for (int u = 0; u < 4; u++)
                    zs[(rh0 + u) * 128 + col] = sigmoid_f(a[u] + gx1[u]);
            } else {                          // r gate -> rh = r .* h (warps 8-15)
                float4 hv = *(const float4*)&hT[hjdx + rh0];
                float4 o;
                o.x = sigmoid_f(a[0] + gx1[0]) * hv.x;
                o.y = sigmoid_f(a[1] + gx1[1]) * hv.y;
                o.z = sigmoid_f(a[2] + gx1[2]) * hv.z;
                o.w = sigmoid_f(a[3] + gx1[3]) * hv.w;
                *(float4*)&rhT[rjdx + rh0] = o;
            }
        }

        // prefetch gx1 for step t+1 (gx1 regs dead; ~700 cyc of cover)
        if (t + 1 < TT) {
            const float* gxn = g_gx + ((size_t)(t + 1) * BB + b0) * GG;
            #pragma unroll
            for (int u = 0; u < 4; u++) gx1[u] = __ldg(gxn + (rh0 + u) * GG + col);
        }
        __syncthreads();

        // ---- phase 2: a-gate partial dots over this lane's k-quarter ----
        u64 p2[4] = {0ULL, 0ULL, 0ULL, 0ULL};
        {
            const float* rp = rhT + kq * 8;
            #pragma unroll
            for (int i = 0; i < 32; i++) {
                ulonglong2 r0 = *(const ulonglong2*)(rp + i * 32);
                ulonglong2 r1 = *(const ulonglong2*)(rp + i * 32 + 4);
                u64 wd = dup2(wa[i]);
                ffma2(p2[0], r0.x, wd);
                ffma2(p2[1], r0.y, wd);
                ffma2(p2[2], r1.x, wd);
                ffma2(p2[3], r1.y, wd);
            }
        }
        // combine across 4 k-quarters (lane bits 3,4)
        #pragma unroll
        for (int q = 0; q < 4; q++) {
            fadd2(p2[q], shfl_xor_u64(p2[q], 8));
            fadd2(p2[q], shfl_xor_u64(p2[q], 16));
        }

        {
            u64 pc = (kq & 2) ? ((kq & 1) ? p2[3] : p2[2])
                              : ((kq & 1) ? p2[1] : p2[0]);
            float aa0, aa1;
            unpack2(pc, aa0, aa1);
            float z0 = zs[(r0v + 0) * 128 + c2];
            float z1 = zs[(r0v + 1) * 128 + c2];
            float h0 = hT[hidx + r0v + 0];
            float h1 = hT[hidx + r0v + 1];
            float hn0 = fmaf(z0, tanh_f(aa0 + gx2a) - h0, h0);
            float hn1 = fmaf(z1, tanh_f(aa1 + gx2b) - h1, h1);
            hT[hidx + r0v + 0] = hn0;
            hT[hidx + r0v + 1] = hn1;
            size_t yb = ((size_t)t * BB + b0 + r0v) * HH + c2;
            g_ys[yb]      = hn0;
            g_ys[yb + HH] = hn1;
        }
        __syncthreads();
    }
}

// ============================================================================
// Kernel 5: out[b,p] = sum_t sum_j ys[t,b,j]*W2[t,j,p] + bias.  (unchanged)
// ============================================================================
__global__ void __launch_bounds__(512, 1) fc_kernel(float* __restrict__ out)
{
    __shared__ float red[8 * HOR * 4];

    const int tid = threadIdx.x;
    const int j   = tid & 127;
    const int g   = tid >> 7;
    const int b0  = blockIdx.x * 8;
    const int lane = tid & 31;
    const int jblk = (j >> 5);

    u64 acc[2][12];
    #pragma unroll
    for (int u = 0; u < 2; u++)
        #pragma unroll
        for (int q = 0; q < 12; q++) acc[u][q] = 0ULL;

    #pragma unroll 2
    for (int t = 0; t < TT; t++) {
        const float* ysp = g_ys + ((size_t)t * BB + b0 + 2 * g) * HH + j;
        float y0 = __ldg(ysp);
        float y1 = __ldg(ysp + HH);
        const ulonglong2* wp = (const ulonglong2*)(g_W2 + ((size_t)t * HH + j) * HOR);
        ulonglong2 w0 = wp[0], w1 = wp[1], w2 = wp[2],
                   w3 = wp[3], w4 = wp[4], w5 = wp[5];
        u64 wq[12] = {w0.x, w0.y, w1.x, w1.y, w2.x, w2.y,
                      w3.x, w3.y, w4.x, w4.y, w5.x, w5.y};
        u64 y0d = dup2(y0), y1d = dup2(y1);
        #pragma unroll
        for (int q = 0; q < 12; q++) {
            ffma2(acc[0][q], y0d, wq[q]);
            ffma2(acc[1][q], y1d, wq[q]);
        }
    }

    #pragma unroll
    for (int u = 0; u < 2; u++)
        #pragma unroll
        for (int q = 0; q < 12; q++) {
            fadd2(acc[u][q], shfl_xor_u64(acc[u][q], 1));
            fadd2(acc[u][q], shfl_xor_u64(acc[u][q], 2));
            fadd2(acc[u][q], shfl_xor_u64(acc[u][q], 4));
            fadd2(acc[u][q], shfl_xor_u64(acc[u][q], 8));
            fadd2(acc[u][q], shfl_xor_u64(acc[u][q], 16));
        }

    if (lane == 0) {
        #pragma unroll
        for (int u = 0; u < 2; u++) {
            int row = 2 * g + u;
            #pragma unroll
            for (int q = 0; q < 12; q++) {
                float v0, v1;
                unpack2(acc[u][q], v0, v1);
                red[(row * HOR + 2 * q + 0) * 4 + jblk] = v0;
                red[(row * HOR + 2 * q + 1) * 4 + jblk] = v1;
            }
        }
    }
    __syncthreads();

    if (tid < 8 * HOR) {
        int row = tid / HOR;
        int p   = tid - row * HOR;
        const float* pp = red + (row * HOR + p) * 4;
        float s = ((pp[0] + pp[1]) + pp[2]) + pp[3];
        out[(size_t)(b0 + row) * HOR + p] = s + g_final_bias[p];
    }
}

// ============================================================================
// launch
// ============================================================================
extern "C" void kernel_launch(void* const* d_in, const int* in_sizes, int n_in,
                              void* d_out, int out_size)
{
    const float* x     = (const float*)d_in[0];
    const float* w_i   = (const float*)d_in[1];
    const float* w_h   = (const float*)d_in[2];
    const float* bvec  = (const float*)d_in[3];
    const float* mlp_w = (const float*)d_in[4];
    const float* mlp_b = (const float*)d_in[5];
    const float* fc_w  = (const float*)d_in[6];
    const float* fc_b  = (const float*)d_in[7];
    const float* out_w = (const float*)d_in[8];
    const float* out_b = (const float*)d_in[9];
    float* out = (float*)d_out;

    const int smem_w2  = (3072 + 12288 + 1024) * 4;   // 65536
    const int smem_gx  = (128 * XT_LD + 128 * GG) * 4;// 231424

    cudaFuncSetAttribute(w2_kernel,  cudaFuncAttributeMaxDynamicSharedMemorySize, smem_w2);
    cudaFuncSetAttribute(gx_kernel,  cudaFuncAttributeMaxDynamicSharedMemorySize, smem_gx);

    w2_kernel<<<TT, 256, smem_w2>>>(mlp_w, mlp_b, fc_w, out_w);
    bias_final_kernel<<<1, 32>>>(fc_b, out_w, out_b);
    gx_kernel<<<(BB * TT) / 64, 256, smem_gx>>>(x, w_i, bvec);
    rec_kernel<<<BB / 8, 512>>>(w_h);
    fc_kernel<<<BB / 8, 512>>>(out);
}

// round 8
// speedup vs baseline: 1.6575x; 1.0750x over previous
#include <cuda_runtime.h>
#include <cuda_bf16.h>
#include <cstdint>

// Problem constants (fixed by the dataset)
#define BB   1024
#define TT   256
#define INDIM 128
#define HH   128
#define GG   384      // 3*H
#define HOR  24

// ---------------- scratch (device globals; no allocations allowed) ----------
__device__ float g_gx[(size_t)TT * BB * GG];        // 384 MB: x@w_i + b, [t][b][g]
__device__ float g_ys[(size_t)TT * BB * HH];        // 128 MB: hidden states, [t][b][j]
__device__ float g_W2[(size_t)TT * HH * HOR];       // 3 MB: folded weights, [t][j][p]
__device__ float g_bias_part[TT * HOR];
__device__ float g_final_bias[HOR];

// ---------------- packed f32x2 helpers (bit-exact vs 2x scalar) -------------
typedef unsigned long long u64;

__device__ __forceinline__ u64 pack2(float lo, float hi) {
    u64 r; asm("mov.b64 %0, {%1, %2};" : "=l"(r) : "f"(lo), "f"(hi)); return r;
}
__device__ __forceinline__ u64 dup2(float v) {
    u64 r; asm("mov.b64 %0, {%1, %1};" : "=l"(r) : "f"(v)); return r;
}
__device__ __forceinline__ void unpack2(u64 v, float& lo, float& hi) {
    asm("mov.b64 {%0, %1}, %2;" : "=f"(lo), "=f"(hi) : "l"(v));
}
__device__ __forceinline__ void ffma2(u64& d, u64 a, u64 b) {
    asm("fma.rn.f32x2 %0, %1, %2, %0;" : "+l"(d) : "l"(a), "l"(b));
}
__device__ __forceinline__ void fadd2(u64& d, u64 a) {
    asm("add.rn.f32x2 %0, %0, %1;" : "+l"(d) : "l"(a));
}
__device__ __forceinline__ u64 shfl_xor_u64(u64 v, int m) {
    uint32_t lo = (uint32_t)v, hi = (uint32_t)(v >> 32);
    lo = __shfl_xor_sync(0xffffffffu, lo, m);
    hi = __shfl_xor_sync(0xffffffffu, hi, m);
    return ((u64)hi << 32) | (u64)lo;
}

// ---------------- activation helpers ----------------------------------------
__device__ __forceinline__ float sigmoid_f(float x) {
    return 1.0f / (1.0f + __expf(-x));
}
__device__ __forceinline__ float tanh_f(float x) {
    float ax = fabsf(x);
    float e  = __expf(2.0f * ax);
    float r  = 1.0f - 2.0f / (e + 1.0f);
    return copysignf(r, x);
}

// ============================================================================
// Kernel 1: fold  W2_t = mlp_w @ (fc_w_t @ out_w)  and bias partial per t.
// ============================================================================
__global__ void __launch_bounds__(256) w2_kernel(
    const float* __restrict__ mlp_w,   // [128,512]
    const float* __restrict__ mlp_b,   // [512]
    const float* __restrict__ fc_w,    // [131072,128]
    const float* __restrict__ out_w)   // [128,24]
{
    extern __shared__ float sm[];
    float* ows    = sm;                 // 3072
    float* P      = sm + 3072;          // 12288
    float* rowbuf = sm + 3072 + 12288;  // 1024
    const int tid  = threadIdx.x;
    const int t    = blockIdx.x;
    const int warp = tid >> 5;
    const int lane = tid & 31;

    for (int i = tid; i < HH * HOR; i += 256) ows[i] = out_w[i];
    __syncthreads();

    const float* fcb = fc_w + (size_t)t * 512 * HH;
    for (int j = warp; j < 512; j += 8) {
        float4 v = ((const float4*)(fcb + (size_t)j * HH))[lane];
        ((float4*)(rowbuf + warp * 128))[lane] = v;
        __syncwarp();
        if (lane < HOR) {
            const float* rb = rowbuf + warp * 128;
            float acc = 0.0f;
            #pragma unroll 4
            for (int k = 0; k < 128; k++) acc = fmaf(rb[k], ows[k * HOR + lane], acc);
            P[j * HOR + lane] = acc;
        }
        __syncwarp();
    }
    __syncthreads();

    if (warp == 0 && lane < HOR) {
        float acc = 0.0f;
        for (int j = 0; j < 512; j++) acc = fmaf(mlp_b[j], P[j * HOR + lane], acc);
        g_bias_part[t * HOR + lane] = acc;
    }

    const int i  = tid & 127;
    const int p0 = (tid >> 7) * 12;
    float acc[12];
    #pragma unroll
    for (int q = 0; q < 12; q++) acc[q] = 0.0f;
    const float* mw = mlp_w + (size_t)i * 512;
    for (int j = 0; j < 512; j++) {
        float m = mw[j];
        const float* pr = P + j * HOR + p0;
        #pragma unroll
        for (int q = 0; q < 12; q++) acc[q] = fmaf(m, pr[q], acc[q]);
    }
    float* dst = g_W2 + ((size_t)t * HH + i) * HOR + p0;
    #pragma unroll
    for (int q = 0; q < 12; q++) dst[q] = acc[q];
}

// ============================================================================
// Kernel 2: final bias = sum_t bias_part + fc_b@out_w + out_b
// ============================================================================
__global__ void bias_final_kernel(const float* __restrict__ fc_b,
                                  const float* __restrict__ out_w,
                                  const float* __restrict__ out_b)
{
    int p = threadIdx.x;
    if (p >= HOR) return;
    float s = out_b[p];
    for (int t = 0; t < TT; t++) s += g_bias_part[t * HOR + p];
    for (int o = 0; o < HH; o++) s = fmaf(fc_b[o], out_w[o * HOR + p], s);
    g_final_bias[p] = s;
}

// ============================================================================
// Kernel 3 (v5): gx = x @ w_i + b, GATE-SPLIT: CTA = 64 rows x 1 gate (128
// cols). smem 98KB -> 2 CTAs/SM (4 warps/SMSP). Small accumulators (32 regs),
// no spills. grid = 4096 tiles x 3 gates.
// ============================================================================
#define XT_LD 68
__global__ void __launch_bounds__(256, 2) gx_kernel(
    const float* __restrict__ x,     // [B][T][128]
    const float* __restrict__ w_i,   // [128][384]
    const float* __restrict__ bvec)  // [384]
{
    extern __shared__ float sm[];
    float* xT = sm;                        // 128*68 floats
    float* ws = sm + 128 * XT_LD;          // 128*128 floats
    const int tid  = threadIdx.x;
    const int gate = blockIdx.x % 3;
    const int m0   = (blockIdx.x / 3) * 64;

    // stage x tile transposed: xT[k][m]
    {
        int row = tid >> 2;
        int k0  = (tid & 3) * 32;
        const float* xrow = x + (size_t)(m0 + row) * INDIM + k0;
        #pragma unroll
        for (int u = 0; u < 8; u++) {
            float4 v = *(const float4*)(xrow + u * 4);
            int k = k0 + u * 4;
            xT[(k + 0) * XT_LD + row] = v.x;
            xT[(k + 1) * XT_LD + row] = v.y;
            xT[(k + 2) * XT_LD + row] = v.z;
            xT[(k + 3) * XT_LD + row] = v.w;
        }
    }
    // stage this gate's w_i slice: ws[k][c] (128x128)
    {
        const float4* src = (const float4*)(w_i + gate * 128);
        float4* dst = (float4*)ws;
        for (int idx = tid; idx < (128 * 128) / 4; idx += 256) {
            int k  = idx >> 5;
            int c4 = idx & 31;
            dst[idx] = src[(size_t)k * 96 + c4];
        }
    }
    __syncthreads();

    const int c   = tid & 31;          // cols 4c..4c+3 of this gate
    const int mr0 = (tid >> 5) * 8;    // 8 rows per thread
    u64 acc2[8][2];
    #pragma unroll
    for (int r = 0; r < 8; r++) { acc2[r][0] = 0ULL; acc2[r][1] = 0ULL; }

    #pragma unroll 4
    for (int k = 0; k < 128; k++) {
        float4 xa = *(const float4*)&xT[k * XT_LD + mr0];
        float4 xb = *(const float4*)&xT[k * XT_LD + mr0 + 4];
        ulonglong2 wg = *(const ulonglong2*)&ws[k * 128 + 4 * c];
        u64 xd[8];
        xd[0] = dup2(xa.x); xd[1] = dup2(xa.y); xd[2] = dup2(xa.z); xd[3] = dup2(xa.w);
        xd[4] = dup2(xb.x); xd[5] = dup2(xb.y); xd[6] = dup2(xb.z); xd[7] = dup2(xb.w);
        #pragma unroll
        for (int r = 0; r < 8; r++) {
            ffma2(acc2[r][0], xd[r], wg.x);
            ffma2(acc2[r][1], xd[r], wg.y);
        }
    }

    float bsr[4];
    #pragma unroll
    for (int u = 0; u < 4; u++) bsr[u] = __ldg(bvec + gate * 128 + 4 * c + u);

    #pragma unroll
    for (int r = 0; r < 8; r++) {
        int m  = m0 + mr0 + r;
        int bb = m >> 8;
        int tt = m & 255;
        float v0, v1, v2, v3;
        unpack2(acc2[r][0], v0, v1);
        unpack2(acc2[r][1], v2, v3);
        float4 o;
        o.x = v0 + bsr[0];
        o.y = v1 + bsr[1];
        o.z = v2 + bsr[2];
        o.w = v3 + bsr[3];
        *(float4*)(g_gx + ((size_t)tt * BB + bb) * GG + gate * 128 + 4 * c) = o;
    }
}

// ============================================================================
// Kernel 4 (v7): recurrence. w_h in regs (96), 2-col ownership, deep k-split.
// 128 CTAs x 512 threads, 8 batch rows/CTA, 2 barriers/step.
// Phase 1 (zr): lane = (cc=l&7 -> cols 2cc,2cc+1 of warp's 16; s1=l>>3 k-split
//   4, strided k=4i+s1). Reduce-scatter shuffles land rows 2s1,2s1+1 on owner.
// Phase 2 (a):  lane = (cc2=l&3 -> 2 cols of warp's 8; s3=l>>2 k-split 8,
//   strided k=8i+s3). 2 u64 stages + 1 f32 row-split stage -> row rF on owner.
// Plain smem layouts (strided k gives bank spread for free).
// ============================================================================
__global__ void __launch_bounds__(512, 1) rec_kernel(
    const float* __restrict__ w_h)   // [128][384]
{
    __shared__ float hT[1024];    // [j][r]
    __shared__ float rhT[1024];   // [j][r]
    __shared__ float zs[1024];    // [col][r]

    const int tid = threadIdx.x;
    const int w   = tid >> 5;
    const int l   = tid & 31;
    const int b0  = blockIdx.x * 8;

    // phase-1 identity
    const int colA = w * 16 + 2 * (l & 7);   // cols colA, colA+1
    const int s1   = l >> 3;                 // 0..3 (lane bits 3,4)
    const int rz   = 2 * s1;                 // final rows rz, rz+1
    // phase-2 identity
    const int colB = w * 8 + 2 * (l & 3);    // cols colB, colB+1
    const int s3   = l >> 2;                 // 0..7 (lane bits 2,3,4)
    const int jf2  = 2 * (s3 & 1) + ((s3 >> 1) & 1);
    const int rF   = 2 * jf2 + (s3 >> 2);

    const int jA = colA - 128;               // r-gate j (warps 8..15)

    // ---- weights into registers (strided k) ----
    float wzA[32], wzB[32];
    #pragma unroll
    for (int i = 0; i < 32; i++) {
        wzA[i] = __ldg(w_h + (size_t)(4 * i + s1) * GG + colA);
        wzB[i] = __ldg(w_h + (size_t)(4 * i + s1) * GG + colA + 1);
    }
    float waA[16], waB[16];
    #pragma unroll
    for (int i = 0; i < 16; i++) {
        waA[i] = __ldg(w_h + (size_t)(8 * i + s3) * GG + 256 + colB);
        waB[i] = __ldg(w_h + (size_t)(8 * i + s3) * GG + 256 + colB + 1);
    }

    for (int i = tid; i < 1024; i += 512) hT[i] = 0.0f;
    __syncthreads();

    // prime gx1 for step 0: rows rz,rz+1 at cols colA,colA+1
    float2 g1a, g1b;
    {
        const float* g0 = g_gx + (size_t)b0 * GG;
        g1a = *(const float2*)(g0 + (rz + 0) * GG + colA);
        g1b = *(const float2*)(g0 + (rz + 1) * GG + colA);
    }

    for (int t = 0; t < TT; t++) {
        const float* gxt = g_gx + ((size_t)t * BB + b0) * GG;

        // gx2 for this step (consumed at end of phase 2)
        float2 g2 = *(const float2*)(gxt + rF * GG + 256 + colB);

        // ---- phase 1: zr partial dots, k = 4i + s1 ----
        u64 pA[4] = {0ULL,0ULL,0ULL,0ULL};
        u64 pB[4] = {0ULL,0ULL,0ULL,0ULL};
        #pragma unroll
        for (int i = 0; i < 32; i++) {
            const float* hp = &hT[(4 * i + s1) * 8];
            ulonglong2 h0 = *(const ulonglong2*)hp;
            ulonglong2 h1 = *(const ulonglong2*)(hp + 4);
            u64 wdA = dup2(wzA[i]);
            u64 wdB = dup2(wzB[i]);
            ffma2(pA[0], h0.x, wdA); ffma2(pA[1], h0.y, wdA);
            ffma2(pA[2], h1.x, wdA); ffma2(pA[3], h1.y, wdA);
            ffma2(pB[0], h0.x, wdB); ffma2(pB[1], h0.y, wdB);
            ffma2(pB[2], h1.x, wdB); ffma2(pB[3], h1.y, wdB);
        }
        // combine stage 1 (xor 16 = s1 bit1): keep pair-block (s1&2)
        {
            u64 tA0 = shfl_xor_u64(pA[0], 16), tA1 = shfl_xor_u64(pA[1], 16);
            u64 tA2 = shfl_xor_u64(pA[2], 16), tA3 = shfl_xor_u64(pA[3], 16);
            u64 tB0 = shfl_xor_u64(pB[0], 16), tB1 = shfl_xor_u64(pB[1], 16);
            u64 tB2 = shfl_xor_u64(pB[2], 16), tB3 = shfl_xor_u64(pB[3], 16);
            bool hiB = (s1 & 2) != 0;
            u64 kA0 = hiB ? pA[2] : pA[0], rA0 = hiB ? tA2 : tA0;
            u64 kA1 = hiB ? pA[3] : pA[1], rA1 = hiB ? tA3 : tA1;
            u64 kB0 = hiB ? pB[2] : pB[0], rB0 = hiB ? tB2 : tB0;
            u64 kB1 = hiB ? pB[3] : pB[1], rB1 = hiB ? tB3 : tB1;
            fadd2(kA0, rA0); fadd2(kA1, rA1);
            fadd2(kB0, rB0); fadd2(kB1, rB1);
            // stage 2 (xor 8 = s1 bit0): keep one pair
            u64 uA0 = shfl_xor_u64(kA0, 8), uA1 = shfl_xor_u64(kA1, 8);
            u64 uB0 = shfl_xor_u64(kB0, 8), uB1 = shfl_xor_u64(kB1, 8);
            bool hi0 = (s1 & 1) != 0;
            u64 fA = hi0 ? kA1 : kA0, gA = hi0 ? uA1 : uA0;
            u64 fB = hi0 ? kB1 : kB0, gB = hi0 ? uB1 : uB0;
            fadd2(fA, gA); fadd2(fB, gB);

            float aA0, aA1, aB0, aB1;
            unpack2(fA, aA0, aA1);
            unpack2(fB, aB0, aB1);
            aA0 += g1a.x; aB0 += g1a.y;
            aA1 += g1b.x; aB1 += g1b.y;

            if (colA < 128) {                 // z gate (warps 0..7)
                float2 vA = make_float2(sigmoid_f(aA0), sigmoid_f(aA1));
                float2 vB = make_float2(sigmoid_f(aB0), sigmoid_f(aB1));
                *(float2*)&zs[(colA + 0) * 8 + rz] = vA;
                *(float2*)&zs[(colA + 1) * 8 + rz] = vB;
            } else {                          // r gate -> rh = r .* h
                float2 hA = *(const float2*)&hT[(jA + 0) * 8 + rz];
                float2 hB = *(const float2*)&hT[(jA + 1) * 8 + rz];
                float2 oA = make_float2(sigmoid_f(aA0) * hA.x, sigmoid_f(aA1) * hA.y);
                float2 oB = make_float2(sigmoid_f(aB0) * hB.x, sigmoid_f(aB1) * hB.y);
                *(float2*)&rhT[(jA + 0) * 8 + rz] = oA;
                *(float2*)&rhT[(jA + 1) * 8 + rz] = oB;
            }
        }

        // prefetch gx1 for step t+1
        if (t + 1 < TT) {
            const float* gxn = g_gx + ((size_t)(t + 1) * BB + b0) * GG;
            g1a = *(const float2*)(gxn + (rz + 0) * GG + colA);
            g1b = *(const float2*)(gxn + (rz + 1) * GG + colA);
        }
        __syncthreads();

        // ---- phase 2: a-gate partial dots, k = 8i + s3 ----
        u64 qA[4] = {0ULL,0ULL,0ULL,0ULL};
        u64 qB[4] = {0ULL,0ULL,0ULL,0ULL};
        #pragma unroll
        for (int i = 0; i < 16; i++) {
            const float* rp = &rhT[(8 * i + s3) * 8];
            ulonglong2 r0 = *(const ulonglong2*)rp;
            ulonglong2 r1 = *(const ulonglong2*)(rp + 4);
            u64 wdA = dup2(waA[i]);
            u64 wdB = dup2(waB[i]);
            ffma2(qA[0], r0.x, wdA); ffma2(qA[1], r0.y, wdA);
            ffma2(qA[2], r1.x, wdA); ffma2(qA[3], r1.y, wdA);
            ffma2(qB[0], r0.x, wdB); ffma2(qB[1], r0.y, wdB);
            ffma2(qB[2], r1.x, wdB); ffma2(qB[3], r1.y, wdB);
        }
        float vA, vB;
        {
            // stage 1 (xor 4 = s3 bit0)
            u64 tA0 = shfl_xor_u64(qA[0], 4), tA1 = shfl_xor_u64(qA[1], 4);
            u64 tA2 = shfl_xor_u64(qA[2], 4), tA3 = shfl_xor_u64(qA[3], 4);
            u64 tB0 = shfl_xor_u64(qB[0], 4), tB1 = shfl_xor_u64(qB[1], 4);
            u64 tB2 = shfl_xor_u64(qB[2], 4), tB3 = shfl_xor_u64(qB[3], 4);
            bool hiB = (s3 & 1) != 0;
            u64 kA0 = hiB ? qA[2] : qA[0], rA0 = hiB ? tA2 : tA0;
            u64 kA1 = hiB ? qA[3] : qA[1], rA1 = hiB ? tA3 : tA1;
            u64 kB0 = hiB ? qB[2] : qB[0], rB0 = hiB ? tB2 : tB0;
            u64 kB1 = hiB ? qB[3] : qB[1], rB1 = hiB ? tB3 : tB1;
            fadd2(kA0, rA0); fadd2(kA1, rA1);
            fadd2(kB0, rB0); fadd2(kB1, rB1);
            // stage 2 (xor 8 = s3 bit1)
            u64 uA0 = shfl_xor_u64(kA0, 8), uA1 = shfl_xor_u64(kA1, 8);
            u64 uB0 = shfl_xor_u64(kB0, 8), uB1 = shfl_xor_u64(kB1, 8);
            bool hi1 = ((s3 >> 1) & 1) != 0;
            u64 fA = hi1 ? kA1 : kA0, gA = hi1 ? uA1 : uA0;
            u64 fB = hi1 ? kB1 : kB0, gB = hi1 ? uB1 : uB0;
            fadd2(fA, gA); fadd2(fB, gB);
            // stage 3 (xor 16 = s3 bit2): row split in f32
            float loA, hiA_, loB, hiB_;
            unpack2(fA, loA, hiA_);
            unpack2(fB, loB, hiB_);
            bool top = (s3 & 4) != 0;
            float sendA = top ? loA : hiA_;
            float sendB = top ? loB : hiB_;
            float rcvA = __shfl_xor_sync(0xffffffffu, sendA, 16);
            float rcvB = __shfl_xor_sync(0xffffffffu, sendB, 16);
            vA = (top ? hiA_ : loA) + rcvA;
            vB = (top ? hiB_ : loB) + rcvB;
        }
        // final: tanh + h update + stream ys (thread owns row rF, cols colB..+1)
        {
            float z0 = zs[(colB + 0) * 8 + rF];
            float z1 = zs[(colB + 1) * 8 + rF];
            float h0 = hT[(colB + 0) * 8 + rF];
            float h1 = hT[(colB + 1) * 8 + rF];
            float hn0 = fmaf(z0, tanh_f(vA + g2.x) - h0, h0);
            float hn1 = fmaf(z1, tanh_f(vB + g2.y) - h1, h1);
            hT[(colB + 0) * 8 + rF] = hn0;
            hT[(colB + 1) * 8 + rF] = hn1;
            *(float2*)&g_ys[((size_t)t * BB + b0 + rF) * HH + colB] = make_float2(hn0, hn1);
        }
        __syncthreads();
    }
}

// ============================================================================
// Kernel 5: out[b,p] = sum_t sum_j ys[t,b,j]*W2[t,j,p] + bias.  (unchanged)
// ============================================================================
__global__ void __launch_bounds__(512, 1) fc_kernel(float* __restrict__ out)
{
    __shared__ float red[8 * HOR * 4];

    const int tid = threadIdx.x;
    const int j   = tid & 127;
    const int g   = tid >> 7;
    const int b0  = blockIdx.x * 8;
    const int lane = tid & 31;
    const int jblk = (j >> 5);

    u64 acc[2][12];
    #pragma unroll
    for (int u = 0; u < 2; u++)
        #pragma unroll
        for (int q = 0; q < 12; q++) acc[u][q] = 0ULL;

    #pragma unroll 2
    for (int t = 0; t < TT; t++) {
        const float* ysp = g_ys + ((size_t)t * BB + b0 + 2 * g) * HH + j;
        float y0 = __ldg(ysp);
        float y1 = __ldg(ysp + HH);
        const ulonglong2* wp = (const ulonglong2*)(g_W2 + ((size_t)t * HH + j) * HOR);
        ulonglong2 w0 = wp[0], w1 = wp[1], w2 = wp[2],
                   w3 = wp[3], w4 = wp[4], w5 = wp[5];
        u64 wq[12] = {w0.x, w0.y, w1.x, w1.y, w2.x, w2.y,
                      w3.x, w3.y, w4.x, w4.y, w5.x, w5.y};
        u64 y0d = dup2(y0), y1d = dup2(y1);
        #pragma unroll
        for (int q = 0; q < 12; q++) {
            ffma2(acc[0][q], y0d, wq[q]);
            ffma2(acc[1][q], y1d, wq[q]);
        }
    }

    #pragma unroll
    for (int u = 0; u < 2; u++)
        #pragma unroll
        for (int q = 0; q < 12; q++) {
            fadd2(acc[u][q], shfl_xor_u64(acc[u][q], 1));
            fadd2(acc[u][q], shfl_xor_u64(acc[u][q], 2));
            fadd2(acc[u][q], shfl_xor_u64(acc[u][q], 4));
            fadd2(acc[u][q], shfl_xor_u64(acc[u][q], 8));
            fadd2(acc[u][q], shfl_xor_u64(acc[u][q], 16));
        }

    if (lane == 0) {
        #pragma unroll
        for (int u = 0; u < 2; u++) {
            int row = 2 * g + u;
            #pragma unroll
            for (int q = 0; q < 12; q++) {
                float v0, v1;
                unpack2(acc[u][q], v0, v1);
                red[(row * HOR + 2 * q + 0) * 4 + jblk] = v0;
                red[(row * HOR + 2 * q + 1) * 4 + jblk] = v1;
            }
        }
    }
    __syncthreads();

    if (tid < 8 * HOR) {
        int row = tid / HOR;
        int p   = tid - row * HOR;
        const float* pp = red + (row * HOR + p) * 4;
        float s = ((pp[0] + pp[1]) + pp[2]) + pp[3];
        out[(size_t)(b0 + row) * HOR + p] = s + g_final_bias[p];
    }
}

// ============================================================================
// launch
// ============================================================================
extern "C" void kernel_launch(void* const* d_in, const int* in_sizes, int n_in,
                              void* d_out, int out_size)
{
    const float* x     = (const float*)d_in[0];
    const float* w_i   = (const float*)d_in[1];
    const float* w_h   = (const float*)d_in[2];
    const float* bvec  = (const float*)d_in[3];
    const float* mlp_w = (const float*)d_in[4];
    const float* mlp_b = (const float*)d_in[5];
    const float* fc_w  = (const float*)d_in[6];
    const float* fc_b  = (const float*)d_in[7];
    const float* out_w = (const float*)d_in[8];
    const float* out_b = (const float*)d_in[9];
    float* out = (float*)d_out;

    const int smem_w2  = (3072 + 12288 + 1024) * 4;        // 65536
    const int smem_gx  = (128 * XT_LD + 128 * 128) * 4;    // 100352

    cudaFuncSetAttribute(w2_kernel,  cudaFuncAttributeMaxDynamicSharedMemorySize, smem_w2);
    cudaFuncSetAttribute(gx_kernel,  cudaFuncAttributeMaxDynamicSharedMemorySize, smem_gx);

    w2_kernel<<<TT, 256, smem_w2>>>(mlp_w, mlp_b, fc_w, out_w);
    bias_final_kernel<<<1, 32>>>(fc_b, out_w, out_b);
    gx_kernel<<<(BB * TT / 64) * 3, 256, smem_gx>>>(x, w_i, bvec);
    rec_kernel<<<BB / 8, 512>>>(w_h);
    fc_kernel<<<BB / 8, 512>>>(out);
}

// round 10
// speedup vs baseline: 1.7236x; 1.0399x over previous
#include <cuda_runtime.h>
#include <cuda_bf16.h>
#include <cstdint>

// Problem constants (fixed by the dataset)
#define BB   1024
#define TT   256
#define INDIM 128
#define HH   128
#define GG   384      // 3*H
#define HOR  24

// ---------------- scratch (device globals; no allocations allowed) ----------
__device__ float g_gx[(size_t)TT * BB * GG];        // 384 MB: x@w_i + b, [t][b][g]
__device__ float g_ys[(size_t)TT * BB * HH];        // 128 MB: hidden states, [t][b][j]
__device__ float g_W2[(size_t)TT * HH * HOR];       // 3 MB: folded weights, [t][j][p]
__device__ float g_bias_part[TT * HOR];
__device__ float g_final_bias[HOR];
__device__ __nv_bfloat16 g_whi[GG * INDIM];         // w_i^T hi, [n][k]
__device__ __nv_bfloat16 g_wlo[GG * INDIM];         // w_i^T lo, [n][k]

// ---------------- packed f32x2 helpers (bit-exact vs 2x scalar) -------------
typedef unsigned long long u64;

__device__ __forceinline__ u64 pack2(float lo, float hi) {
    u64 r; asm("mov.b64 %0, {%1, %2};" : "=l"(r) : "f"(lo), "f"(hi)); return r;
}
__device__ __forceinline__ u64 dup2(float v) {
    u64 r; asm("mov.b64 %0, {%1, %1};" : "=l"(r) : "f"(v)); return r;
}
__device__ __forceinline__ void unpack2(u64 v, float& lo, float& hi) {
    asm("mov.b64 {%0, %1}, %2;" : "=f"(lo), "=f"(hi) : "l"(v));
}
__device__ __forceinline__ void ffma2(u64& d, u64 a, u64 b) {
    asm("fma.rn.f32x2 %0, %1, %2, %0;" : "+l"(d) : "l"(a), "l"(b));
}
__device__ __forceinline__ void fadd2(u64& d, u64 a) {
    asm("add.rn.f32x2 %0, %0, %1;" : "+l"(d) : "l"(a));
}
__device__ __forceinline__ u64 shfl_xor_u64(u64 v, int m) {
    uint32_t lo = (uint32_t)v, hi = (uint32_t)(v >> 32);
    lo = __shfl_xor_sync(0xffffffffu, lo, m);
    hi = __shfl_xor_sync(0xffffffffu, hi, m);
    return ((u64)hi << 32) | (u64)lo;
}

// ---------------- mma.sync / ldmatrix helpers (sm_100 baseline ISA) ----------
__device__ __forceinline__ uint32_t smem_u32(const void* p) {
    uint32_t a;
    asm("{ .reg .u64 t; cvta.to.shared.u64 t, %1; cvt.u32.u64 %0, t; }" : "=r"(a) : "l"(p));
    return a;
}
__device__ __forceinline__ void ldsm_x4(uint32_t* r, uint32_t addr) {
    asm volatile("ldmatrix.sync.aligned.m8n8.x4.shared.b16 {%0,%1,%2,%3}, [%4];"
                 : "=r"(r[0]), "=r"(r[1]), "=r"(r[2]), "=r"(r[3]) : "r"(addr));
}
__device__ __forceinline__ void mma_bf16(float* d, const uint32_t* a,
                                         uint32_t b0, uint32_t b1) {
    asm volatile(
        "mma.sync.aligned.m16n8k16.row.col.f32.bf16.bf16.f32 "
        "{%0,%1,%2,%3}, {%4,%5,%6,%7}, {%8,%9}, {%0,%1,%2,%3};"
        : "+f"(d[0]), "+f"(d[1]), "+f"(d[2]), "+f"(d[3])
        : "r"(a[0]), "r"(a[1]), "r"(a[2]), "r"(a[3]), "r"(b0), "r"(b1));
}
// swizzled byte offset for bf16 tile [row][col], 256B rows, 16B chunks
__device__ __forceinline__ uint32_t swz(int row, int c16) {
    return (uint32_t)(row * 256 + ((c16 ^ (row & 7)) << 4));
}

// ---------------- activation helpers ----------------------------------------
__device__ __forceinline__ float sigmoid_f(float x) {
    return 1.0f / (1.0f + __expf(-x));
}
__device__ __forceinline__ float tanh_f(float x) {
    float ax = fabsf(x);
    float e  = __expf(2.0f * ax);
    float r  = 1.0f - 2.0f / (e + 1.0f);
    return copysignf(r, x);
}

// ============================================================================
// Kernel 1: fold  W2_t = mlp_w @ (fc_w_t @ out_w)  and bias partial per t.
// ============================================================================
__global__ void __launch_bounds__(256) w2_kernel(
    const float* __restrict__ mlp_w,   // [128,512]
    const float* __restrict__ mlp_b,   // [512]
    const float* __restrict__ fc_w,    // [131072,128]
    const float* __restrict__ out_w)   // [128,24]
{
    extern __shared__ float sm[];
    float* ows    = sm;
    float* P      = sm + 3072;
    float* rowbuf = sm + 3072 + 12288;
    const int tid  = threadIdx.x;
    const int t    = blockIdx.x;
    const int warp = tid >> 5;
    const int lane = tid & 31;

    for (int i = tid; i < HH * HOR; i += 256) ows[i] = out_w[i];
    __syncthreads();

    const float* fcb = fc_w + (size_t)t * 512 * HH;
    for (int j = warp; j < 512; j += 8) {
        float4 v = ((const float4*)(fcb + (size_t)j * HH))[lane];
        ((float4*)(rowbuf + warp * 128))[lane] = v;
        __syncwarp();
        if (lane < HOR) {
            const float* rb = rowbuf + warp * 128;
            float acc = 0.0f;
            #pragma unroll 4
            for (int k = 0; k < 128; k++) acc = fmaf(rb[k], ows[k * HOR + lane], acc);
            P[j * HOR + lane] = acc;
        }
        __syncwarp();
    }
    __syncthreads();

    if (warp == 0 && lane < HOR) {
        float acc = 0.0f;
        for (int j = 0; j < 512; j++) acc = fmaf(mlp_b[j], P[j * HOR + lane], acc);
        g_bias_part[t * HOR + lane] = acc;
    }

    const int i  = tid & 127;
    const int p0 = (tid >> 7) * 12;
    float acc[12];
    #pragma unroll
    for (int q = 0; q < 12; q++) acc[q] = 0.0f;
    const float* mw = mlp_w + (size_t)i * 512;
    for (int j = 0; j < 512; j++) {
        float m = mw[j];
        const float* pr = P + j * HOR + p0;
        #pragma unroll
        for (int q = 0; q < 12; q++) acc[q] = fmaf(m, pr[q], acc[q]);
    }
    float* dst = g_W2 + ((size_t)t * HH + i) * HOR + p0;
    #pragma unroll
    for (int q = 0; q < 12; q++) dst[q] = acc[q];
}

// ============================================================================
// Kernel 2: final bias = sum_t bias_part + fc_b@out_w + out_b
// ============================================================================
__global__ void bias_final_kernel(const float* __restrict__ fc_b,
                                  const float* __restrict__ out_w,
                                  const float* __restrict__ out_b)
{
    int p = threadIdx.x;
    if (p >= HOR) return;
    float s = out_b[p];
    for (int t = 0; t < TT; t++) s += g_bias_part[t * HOR + p];
    for (int o = 0; o < HH; o++) s = fmaf(fc_b[o], out_w[o * HOR + p], s);
    g_final_bias[p] = s;
}

// ============================================================================
// Kernel 2b: split w_i into bf16 hi/lo, transposed to [n][k] (B operand).
// ============================================================================
__global__ void wsplit_kernel(const float* __restrict__ w_i)  // [128k][384n]
{
    int n = blockIdx.x;     // 0..383
    int k = threadIdx.x;    // 0..127
    float v = w_i[(size_t)k * GG + n];
    __nv_bfloat16 h = __float2bfloat16(v);
    float lo = v - __bfloat162float(h);
    g_whi[n * INDIM + k] = h;
    g_wlo[n * INDIM + k] = __float2bfloat16(lo);
}

// ============================================================================
// Kernel 3 (v7): gx = x @ w_i + b via mma.sync bf16 3-term split.
// CTA = 128 rows x 1 gate (N=128), K=128. 8 warps tiled 4(m)x2(n):
// warp tile m32 x n64. 3 passes (hi*hi, hi*lo, lo*hi) x 8 K-steps,
// fp32 register accumulators. smem: 4 bf16 tiles, XOR-swizzled for ldmatrix.
// ============================================================================
#define GXM_A_HI  0
#define GXM_A_LO  32768
#define GXM_B_HI  65536
#define GXM_B_LO  98304
#define GXM_SMEM  131072

__global__ void __launch_bounds__(256, 1) gx_mma_kernel(
    const float* __restrict__ x,     // [B][T][128] == [m][128]
    const float* __restrict__ bvec)  // [384]
{
    extern __shared__ char smemc[];
    const int tid  = threadIdx.x;
    const int wid  = tid >> 5;
    const int lane = tid & 31;
    const int gate = blockIdx.x % 3;
    const int m0g  = (blockIdx.x / 3) * 128;
    uint32_t sbase = smem_u32(smemc);

    // ---- stage A: read x fp32, split to bf16 hi/lo, store swizzled ----
    {
        int row = tid >> 1, half = tid & 1;
        const float4* xr = (const float4*)(x + (size_t)(m0g + row) * INDIM + half * 64);
        #pragma unroll
        for (int u = 0; u < 8; u++) {
            float4 a = xr[2 * u], b = xr[2 * u + 1];
            float f[8] = {a.x, a.y, a.z, a.w, b.x, b.y, b.z, b.w};
            uint32_t hi[4], lo[4];
            #pragma unroll
            for (int p = 0; p < 4; p++) {
                __nv_bfloat162 h = __floats2bfloat162_rn(f[2*p], f[2*p+1]);
                hi[p] = *(uint32_t*)&h;
                float l0 = f[2*p]     - __bfloat162float(h.x);
                float l1 = f[2*p + 1] - __bfloat162float(h.y);
                __nv_bfloat162 l = __floats2bfloat162_rn(l0, l1);
                lo[p] = *(uint32_t*)&l;
            }
            uint32_t o = swz(row, half * 8 + u);
            *(uint4*)(smemc + GXM_A_HI + o) = make_uint4(hi[0], hi[1], hi[2], hi[3]);
            *(uint4*)(smemc + GXM_A_LO + o) = make_uint4(lo[0], lo[1], lo[2], lo[3]);
        }
    }
    // ---- stage B: pre-split weights (L2), store swizzled ----
    {
        int row = tid >> 1, half = tid & 1;     // row = n index
        size_t src = (size_t)(gate * 128 + row) * INDIM + half * 64;
        const uint4* bh = (const uint4*)(g_whi + src);
        const uint4* bl = (const uint4*)(g_wlo + src);
        #pragma unroll
        for (int u = 0; u < 8; u++) {
            uint32_t o = swz(row, half * 8 + u);
            *(uint4*)(smemc + GXM_B_HI + o) = bh[u];
            *(uint4*)(smemc + GXM_B_LO + o) = bl[u];
        }
    }
    __syncthreads();

    // warp tile: m-rows [m0w, m0w+32), n-cols [n0w, n0w+64)
    const int m0w = (wid & 3) * 32;
    const int n0w = (wid >> 2) * 64;
    const int lr  = lane & 15;          // ldmatrix row-within-16
    const int lc  = lane >> 4;          // ldmatrix chunk select (k8 halves)

    float acc[2][8][4];
    #pragma unroll
    for (int mi = 0; mi < 2; mi++)
        #pragma unroll
        for (int nt = 0; nt < 8; nt++)
            #pragma unroll
            for (int q = 0; q < 4; q++) acc[mi][nt][q] = 0.0f;

    #pragma unroll 1
    for (int pass = 0; pass < 3; pass++) {
        const uint32_t aBase = sbase + ((pass == 2) ? GXM_A_LO : GXM_A_HI);
        const uint32_t bBase = sbase + ((pass == 1) ? GXM_B_LO : GXM_B_HI);
        #pragma unroll
        for (int s = 0; s < 8; s++) {
            const int c16 = 2 * s + lc;
            // A fragments: tiles at m0w, m0w+16
            uint32_t a0[4], a1[4];
            {
                int r0 = m0w + lr;
                ldsm_x4(a0, aBase + swz(r0, c16));
                ldsm_x4(a1, aBase + swz(r0 + 16, c16));
            }
            // B fragments: 4 x (n16 k16) covering n0w..n0w+63
            uint32_t b[4][4];
            #pragma unroll
            for (int q = 0; q < 4; q++) {
                int rn = n0w + q * 16 + lr;
                ldsm_x4(b[q], bBase + swz(rn, c16));
            }
            // 16 mma: 2 m-tiles x 8 n-tiles
            #pragma unroll
            for (int nt = 0; nt < 8; nt++) {
                int q = nt >> 1, sel = nt & 1;
                uint32_t bb0 = b[q][sel];       // (n-half, k0)
                uint32_t bb1 = b[q][sel + 2];   // (n-half, k8)
                mma_bf16(acc[0][nt], a0, bb0, bb1);
                mma_bf16(acc[1][nt], a1, bb0, bb1);
            }
        }
    }

    // ---- epilogue: bias + store ----
    const int colq = (lane & 3) * 2;
    #pragma unroll
    for (int nt = 0; nt < 8; nt++) {
        int c = n0w + nt * 8 + colq;
        float2 bv = *(const float2*)(bvec + gate * 128 + c);
        #pragma unroll
        for (int mi = 0; mi < 2; mi++) {
            int gm0 = m0g + m0w + 16 * mi + (lane >> 2);
            // rows gm0 and gm0+8
            #pragma unroll
            for (int h = 0; h < 2; h++) {
                int gm = gm0 + 8 * h;
                int tt = gm & 255, bb = gm >> 8;
                float2 o;
                o.x = acc[mi][nt][2 * h + 0] + bv.x;
                o.y = acc[mi][nt][2 * h + 1] + bv.y;
                *(float2*)(g_gx + ((size_t)tt * BB + bb) * GG + gate * 128 + c) = o;
            }
        }
    }
}

// ============================================================================
// Kernel 4 (v7, unchanged): recurrence. w_h in regs, deep k-split + shuffles.
// ============================================================================
__global__ void __launch_bounds__(512, 1) rec_kernel(
    const float* __restrict__ w_h)   // [128][384]
{
    __shared__ float hT[1024];    // [j][r]
    __shared__ float rhT[1024];   // [j][r]
    __shared__ float zs[1024];    // [col][r]

    const int tid = threadIdx.x;
    const int w   = tid >> 5;
    const int l   = tid & 31;
    const int b0  = blockIdx.x * 8;

    const int colA = w * 16 + 2 * (l & 7);
    const int s1   = l >> 3;
    const int rz   = 2 * s1;
    const int colB = w * 8 + 2 * (l & 3);
    const int s3   = l >> 2;
    const int jf2  = 2 * (s3 & 1) + ((s3 >> 1) & 1);
    const int rF   = 2 * jf2 + (s3 >> 2);
    const int jA   = colA - 128;

    float wzA[32], wzB[32];
    #pragma unroll
    for (int i = 0; i < 32; i++) {
        wzA[i] = __ldg(w_h + (size_t)(4 * i + s1) * GG + colA);
        wzB[i] = __ldg(w_h + (size_t)(4 * i + s1) * GG + colA + 1);
    }
    float waA[16], waB[16];
    #pragma unroll
    for (int i = 0; i < 16; i++) {
        waA[i] = __ldg(w_h + (size_t)(8 * i + s3) * GG + 256 + colB);
        waB[i] = __ldg(w_h + (size_t)(8 * i + s3) * GG + 256 + colB + 1);
    }

    for (int i = tid; i < 1024; i += 512) hT[i] = 0.0f;
    __syncthreads();

    float2 g1a, g1b;
    {
        const float* g0 = g_gx + (size_t)b0 * GG;
        g1a = *(const float2*)(g0 + (rz + 0) * GG + colA);
        g1b = *(const float2*)(g0 + (rz + 1) * GG + colA);
    }

    for (int t = 0; t < TT; t++) {
        const float* gxt = g_gx + ((size_t)t * BB + b0) * GG;
        float2 g2 = *(const float2*)(gxt + rF * GG + 256 + colB);

        u64 pA[4] = {0ULL,0ULL,0ULL,0ULL};
        u64 pB[4] = {0ULL,0ULL,0ULL,0ULL};
        #pragma unroll
        for (int i = 0; i < 32; i++) {
            const float* hp = &hT[(4 * i + s1) * 8];
            ulonglong2 h0 = *(const ulonglong2*)hp;
            ulonglong2 h1 = *(const ulonglong2*)(hp + 4);
            u64 wdA = dup2(wzA[i]);
            u64 wdB = dup2(wzB[i]);
            ffma2(pA[0], h0.x, wdA); ffma2(pA[1], h0.y, wdA);
            ffma2(pA[2], h1.x, wdA); ffma2(pA[3], h1.y, wdA);
            ffma2(pB[0], h0.x, wdB); ffma2(pB[1], h0.y, wdB);
            ffma2(pB[2], h1.x, wdB); ffma2(pB[3], h1.y, wdB);
        }
        {
            u64 tA0 = shfl_xor_u64(pA[0], 16), tA1 = shfl_xor_u64(pA[1], 16);
            u64 tA2 = shfl_xor_u64(pA[2], 16), tA3 = shfl_xor_u64(pA[3], 16);
            u64 tB0 = shfl_xor_u64(pB[0], 16), tB1 = shfl_xor_u64(pB[1], 16);
            u64 tB2 = shfl_xor_u64(pB[2], 16), tB3 = shfl_xor_u64(pB[3], 16);
            bool hiB = (s1 & 2) != 0;
            u64 kA0 = hiB ? pA[2] : pA[0], rA0 = hiB ? tA2 : tA0;
            u64 kA1 = hiB ? pA[3] : pA[1], rA1 = hiB ? tA3 : tA1;
            u64 kB0 = hiB ? pB[2] : pB[0], rB0 = hiB ? tB2 : tB0;
            u64 kB1 = hiB ? pB[3] : pB[1], rB1 = hiB ? tB3 : tB1;
            fadd2(kA0, rA0); fadd2(kA1, rA1);
            fadd2(kB0, rB0); fadd2(kB1, rB1);
            u64 uA0 = shfl_xor_u64(kA0, 8), uA1 = shfl_xor_u64(kA1, 8);
            u64 uB0 = shfl_xor_u64(kB0, 8), uB1 = shfl_xor_u64(kB1, 8);
            bool hi0 = (s1 & 1) != 0;
            u64 fA = hi0 ? kA1 : kA0, gA = hi0 ? uA1 : uA0;
            u64 fB = hi0 ? kB1 : kB0, gB = hi0 ? uB1 : uB0;
            fadd2(fA, gA); fadd2(fB, gB);

            float aA0, aA1, aB0, aB1;
            unpack2(fA, aA0, aA1);
            unpack2(fB, aB0, aB1);
            aA0 += g1a.x; aB0 += g1a.y;
            aA1 += g1b.x; aB1 += g1b.y;

            if (colA < 128) {
                float2 vA = make_float2(sigmoid_f(aA0), sigmoid_f(aA1));
                float2 vB = make_float2(sigmoid_f(aB0), sigmoid_f(aB1));
                *(float2*)&zs[(colA + 0) * 8 + rz] = vA;
                *(float2*)&zs[(colA + 1) * 8 + rz] = vB;
            } else {
                float2 hA = *(const float2*)&hT[(jA + 0) * 8 + rz];
                float2 hB = *(const float2*)&hT[(jA + 1) * 8 + rz];
                float2 oA = make_float2(sigmoid_f(aA0) * hA.x, sigmoid_f(aA1) * hA.y);
                float2 oB = make_float2(sigmoid_f(aB0) * hB.x, sigmoid_f(aB1) * hB.y);
                *(float2*)&rhT[(jA + 0) * 8 + rz] = oA;
                *(float2*)&rhT[(jA + 1) * 8 + rz] = oB;
            }
        }

        if (t + 1 < TT) {
            const float* gxn = g_gx + ((size_t)(t + 1) * BB + b0) * GG;
            g1a = *(const float2*)(gxn + (rz + 0) * GG + colA);
            g1b = *(const float2*)(gxn + (rz + 1) * GG + colA);
        }
        __syncthreads();

        u64 qA[4] = {0ULL,0ULL,0ULL,0ULL};
        u64 qB[4] = {0ULL,0ULL,0ULL,0ULL};
        #pragma unroll
        for (int i = 0; i < 16; i++) {
            const float* rp = &rhT[(8 * i + s3) * 8];
            ulonglong2 r0 = *(const ulonglong2*)rp;
            ulonglong2 r1 = *(const ulonglong2*)(rp + 4);
            u64 wdA = dup2(waA[i]);
            u64 wdB = dup2(waB[i]);
            ffma2(qA[0], r0.x, wdA); ffma2(qA[1], r0.y, wdA);
            ffma2(qA[2], r1.x, wdA); ffma2(qA[3], r1.y, wdA);
            ffma2(qB[0], r0.x, wdB); ffma2(qB[1], r0.y, wdB);
            ffma2(qB[2], r1.x, wdB); ffma2(qB[3], r1.y, wdB);
        }
        float vA, vB;
        {
            u64 tA0 = shfl_xor_u64(qA[0], 4), tA1 = shfl_xor_u64(qA[1], 4);
            u64 tA2 = shfl_xor_u64(qA[2], 4), tA3 = shfl_xor_u64(qA[3], 4);
            u64 tB0 = shfl_xor_u64(qB[0], 4), tB1 = shfl_xor_u64(qB[1], 4);
            u64 tB2 = shfl_xor_u64(qB[2], 4), tB3 = shfl_xor_u64(qB[3], 4);
            bool hiB = (s3 & 1) != 0;
            u64 kA0 = hiB ? qA[2] : qA[0], rA0 = hiB ? tA2 : tA0;
            u64 kA1 = hiB ? qA[3] : qA[1], rA1 = hiB ? tA3 : tA1;
            u64 kB0 = hiB ? qB[2] : qB[0], rB0 = hiB ? tB2 : tB0;
            u64 kB1 = hiB ? qB[3] : qB[1], rB1 = hiB ? tB3 : tB1;
            fadd2(kA0, rA0); fadd2(kA1, rA1);
            fadd2(kB0, rB0); fadd2(kB1, rB1);
            u64 uA0 = shfl_xor_u64(kA0, 8), uA1 = shfl_xor_u64(kA1, 8);
            u64 uB0 = shfl_xor_u64(kB0, 8), uB1 = shfl_xor_u64(kB1, 8);
            bool hi1 = ((s3 >> 1) & 1) != 0;
            u64 fA = hi1 ? kA1 : kA0, gA = hi1 ? uA1 : uA0;
            u64 fB = hi1 ? kB1 : kB0, gB = hi1 ? uB1 : uB0;
            fadd2(fA, gA); fadd2(fB, gB);
            float loA, hiA_, loB, hiB_;
            unpack2(fA, loA, hiA_);
            unpack2(fB, loB, hiB_);
            bool top = (s3 & 4) != 0;
            float sendA = top ? loA : hiA_;
            float sendB = top ? loB : hiB_;
            float rcvA = __shfl_xor_sync(0xffffffffu, sendA, 16);
            float rcvB = __shfl_xor_sync(0xffffffffu, sendB, 16);
            vA = (top ? hiA_ : loA) + rcvA;
            vB = (top ? hiB_ : loB) + rcvB;
        }
        {
            float z0 = zs[(colB + 0) * 8 + rF];
            float z1 = zs[(colB + 1) * 8 + rF];
            float h0 = hT[(colB + 0) * 8 + rF];
            float h1 = hT[(colB + 1) * 8 + rF];
            float hn0 = fmaf(z0, tanh_f(vA + g2.x) - h0, h0);
            float hn1 = fmaf(z1, tanh_f(vB + g2.y) - h1, h1);
            hT[(colB + 0) * 8 + rF] = hn0;
            hT[(colB + 1) * 8 + rF] = hn1;
            *(float2*)&g_ys[((size_t)t * BB + b0 + rF) * HH + colB] = make_float2(hn0, hn1);
        }
        __syncthreads();
    }
}

// ============================================================================
// Kernel 5 (unchanged): out[b,p] = sum_t sum_j ys[t,b,j]*W2[t,j,p] + bias.
// ============================================================================
__global__ void __launch_bounds__(512, 1) fc_kernel(float* __restrict__ out)
{
    __shared__ float red[8 * HOR * 4];

    const int tid = threadIdx.x;
    const int j   = tid & 127;
    const int g   = tid >> 7;
    const int b0  = blockIdx.x * 8;
    const int lane = tid & 31;
    const int jblk = (j >> 5);

    u64 acc[2][12];
    #pragma unroll
    for (int u = 0; u < 2; u++)
        #pragma unroll
        for (int q = 0; q < 12; q++) acc[u][q] = 0ULL;

    #pragma unroll 2
    for (int t = 0; t < TT; t++) {
        const float* ysp = g_ys + ((size_t)t * BB + b0 + 2 * g) * HH + j;
        float y0 = __ldg(ysp);
        float y1 = __ldg(ysp + HH);
        const ulonglong2* wp = (const ulonglong2*)(g_W2 + ((size_t)t * HH + j) * HOR);
        ulonglong2 w0 = wp[0], w1 = wp[1], w2 = wp[2],
                   w3 = wp[3], w4 = wp[4], w5 = wp[5];
        u64 wq[12] = {w0.x, w0.y, w1.x, w1.y, w2.x, w2.y,
                      w3.x, w3.y, w4.x, w4.y, w5.x, w5.y};
        u64 y0d = dup2(y0), y1d = dup2(y1);
        #pragma unroll
        for (int q = 0; q < 12; q++) {
            ffma2(acc[0][q], y0d, wq[q]);
            ffma2(acc[1][q], y1d, wq[q]);
        }
    }

    #pragma unroll
    for (int u = 0; u < 2; u++)
        #pragma unroll
        for (int q = 0; q < 12; q++) {
            fadd2(acc[u][q], shfl_xor_u64(acc[u][q], 1));
            fadd2(acc[u][q], shfl_xor_u64(acc[u][q], 2));
            fadd2(acc[u][q], shfl_xor_u64(acc[u][q], 4));
            fadd2(acc[u][q], shfl_xor_u64(acc[u][q], 8));
            fadd2(acc[u][q], shfl_xor_u64(acc[u][q], 16));
        }

    if (lane == 0) {
        #pragma unroll
        for (int u = 0; u < 2; u++) {
            int row = 2 * g + u;
            #pragma unroll
            for (int q = 0; q < 12; q++) {
                float v0, v1;
                unpack2(acc[u][q], v0, v1);
                red[(row * HOR + 2 * q + 0) * 4 + jblk] = v0;
                red[(row * HOR + 2 * q + 1) * 4 + jblk] = v1;
            }
        }
    }
    __syncthreads();

    if (tid < 8 * HOR) {
        int row = tid / HOR;
        int p   = tid - row * HOR;
        const float* pp = red + (row * HOR + p) * 4;
        float s = ((pp[0] + pp[1]) + pp[2]) + pp[3];
        out[(size_t)(b0 + row) * HOR + p] = s + g_final_bias[p];
    }
}

// ============================================================================
// launch
// ============================================================================
extern "C" void kernel_launch(void* const* d_in, const int* in_sizes, int n_in,
                              void* d_out, int out_size)
{
    const float* x     = (const float*)d_in[0];
    const float* w_i   = (const float*)d_in[1];
    const float* w_h   = (const float*)d_in[2];
    const float* bvec  = (const float*)d_in[3];
    const float* mlp_w = (const float*)d_in[4];
    const float* mlp_b = (const float*)d_in[5];
    const float* fc_w  = (const float*)d_in[6];
    const float* fc_b  = (const float*)d_in[7];
    const float* out_w = (const float*)d_in[8];
    const float* out_b = (const float*)d_in[9];
    float* out = (float*)d_out;

    const int smem_w2 = (3072 + 12288 + 1024) * 4;   // 65536

    cudaFuncSetAttribute(w2_kernel,     cudaFuncAttributeMaxDynamicSharedMemorySize, smem_w2);
    cudaFuncSetAttribute(gx_mma_kernel, cudaFuncAttributeMaxDynamicSharedMemorySize, GXM_SMEM);

    w2_kernel<<<TT, 256, smem_w2>>>(mlp_w, mlp_b, fc_w, out_w);
    bias_final_kernel<<<1, 32>>>(fc_b, out_w, out_b);
    wsplit_kernel<<<GG, 128>>>(w_i);
    gx_mma_kernel<<<(BB * TT / 128) * 3, 256, GXM_SMEM>>>(x, bvec);
    rec_kernel<<<BB / 8, 512>>>(w_h);
    fc_kernel<<<BB / 8, 512>>>(out);
}